// round 2
// baseline (speedup 1.0000x reference)
#include <cuda_runtime.h>
#include <math.h>

#define D_MODEL   1024
#define D_STATE   16
#define D_CONV    4
#define HEADDIM   64
#define CHUNK     64
#define D_INNER   2048
#define NHEADS    32
#define CONV_DIM  2080          // D_INNER + 2*D_STATE
#define D_IN_PROJ 4160          // 2*D_INNER + 2*D_STATE + NHEADS
#define BATCH     2
#define SEQ       4096
#define NCHUNK    (SEQ / CHUNK) // 64
#define MTOT      (BATCH * SEQ) // 8192

// ---------------- scratch (device globals; no allocation allowed) -----------
__device__ float g_zxbcdt[(size_t)MTOT * D_IN_PROJ];           // 136 MB
__device__ float g_xBC[(size_t)MTOT * CONV_DIM];               // 68 MB (post conv+silu)
__device__ float g_dt[(size_t)MTOT * NHEADS];                  // softplus(dt)
__device__ float g_Acum[(size_t)BATCH * NCHUNK * NHEADS * CHUNK];
__device__ float g_cs[(size_t)BATCH * NCHUNK * NHEADS * HEADDIM * D_STATE]; // chunk states
__device__ float g_sp[(size_t)BATCH * NCHUNK * NHEADS * HEADDIM * D_STATE]; // prefix states
__device__ float g_y[(size_t)MTOT * D_INNER];                  // 64 MB

// ---------------- GEMM: C[M,N] = A[M,K] @ B[N,K]^T (both K-contiguous) ------
// 128x128 block, 8x8 per thread, BK=8, 256 threads. M % 128 == 0 assumed.
__global__ __launch_bounds__(256) void sgemm_nt(
    const float* __restrict__ A, const float* __restrict__ B,
    float* __restrict__ C, int M, int N, int K)
{
    __shared__ float As[8][128];
    __shared__ float Bs[8][128];

    const int tid  = threadIdx.x;
    const int tx   = tid & 15;       // 0..15  -> N micro
    const int ty   = tid >> 4;       // 0..15  -> M micro
    const int brow = blockIdx.y * 128;
    const int bcol = blockIdx.x * 128;

    const int lrow = tid >> 1;        // 0..127
    const int lcol = (tid & 1) * 4;   // 0 or 4

    float acc[8][8];
    #pragma unroll
    for (int i = 0; i < 8; i++)
        #pragma unroll
        for (int j = 0; j < 8; j++) acc[i][j] = 0.f;

    const int gm_l = brow + lrow;
    const int gn_l = bcol + lrow;

    for (int k0 = 0; k0 < K; k0 += 8) {
        float4 av = *(const float4*)(A + (size_t)gm_l * K + k0 + lcol);
        float4 bv = make_float4(0.f, 0.f, 0.f, 0.f);
        if (gn_l < N)
            bv = *(const float4*)(B + (size_t)gn_l * K + k0 + lcol);

        As[lcol + 0][lrow] = av.x; As[lcol + 1][lrow] = av.y;
        As[lcol + 2][lrow] = av.z; As[lcol + 3][lrow] = av.w;
        Bs[lcol + 0][lrow] = bv.x; Bs[lcol + 1][lrow] = bv.y;
        Bs[lcol + 2][lrow] = bv.z; Bs[lcol + 3][lrow] = bv.w;
        __syncthreads();

        #pragma unroll
        for (int kk = 0; kk < 8; kk++) {
            float ar[8], br[8];
            #pragma unroll
            for (int i = 0; i < 8; i++) ar[i] = As[kk][ty * 8 + i];
            #pragma unroll
            for (int j = 0; j < 8; j++) br[j] = Bs[kk][tx * 8 + j];
            #pragma unroll
            for (int i = 0; i < 8; i++)
                #pragma unroll
                for (int j = 0; j < 8; j++)
                    acc[i][j] += ar[i] * br[j];
        }
        __syncthreads();
    }

    #pragma unroll
    for (int i = 0; i < 8; i++) {
        int gm = brow + ty * 8 + i;
        #pragma unroll
        for (int j = 0; j < 8; j++) {
            int gn = bcol + tx * 8 + j;
            if (gn < N) C[(size_t)gm * N + gn] = acc[i][j];
        }
    }
}

// ---------------- depthwise causal conv(4) + bias + SiLU --------------------
__global__ void conv_silu_kernel(const float* __restrict__ conv_w,
                                 const float* __restrict__ conv_b)
{
    int idx = blockIdx.x * blockDim.x + threadIdx.x;
    if (idx >= MTOT * CONV_DIM) return;
    int c = idx % CONV_DIM;
    int m = idx / CONV_DIM;          // b*SEQ + l
    int l = m & (SEQ - 1);

    float acc = conv_b[c];
    #pragma unroll
    for (int j = 0; j < D_CONV; j++) {
        int lj = l - (D_CONV - 1) + j;
        if (lj >= 0)
            acc += conv_w[c * D_CONV + j] *
                   g_zxbcdt[(size_t)(m - (D_CONV - 1) + j) * D_IN_PROJ + D_INNER + c];
    }
    g_xBC[idx] = acc / (1.f + expf(-acc));   // silu
}

// ---------------- dt = softplus(raw + bias) ---------------------------------
__global__ void dt_kernel(const float* __restrict__ dt_bias)
{
    int idx = blockIdx.x * blockDim.x + threadIdx.x;
    if (idx >= MTOT * NHEADS) return;
    int h = idx & (NHEADS - 1);
    int m = idx >> 5;
    float x = g_zxbcdt[(size_t)m * D_IN_PROJ + (D_IN_PROJ - NHEADS) + h] + dt_bias[h];
    g_dt[idx] = (x > 20.f) ? x : log1pf(expf(x));
}

// ---------------- SSD stage 1: per-chunk diag output + chunk states ---------
__global__ __launch_bounds__(256) void ssd_chunk_kernel(const float* __restrict__ A_log)
{
    __shared__ float xs[CHUNK][HEADDIM];     // x * dt
    __shared__ float Gs[CHUNK][CHUNK];
    __shared__ float Bsh[CHUNK][D_STATE];
    __shared__ float Csh[CHUNK][D_STATE];
    __shared__ float Acum[CHUNK];
    __shared__ float dts[CHUNK];
    __shared__ float decay[CHUNK];

    const int c = blockIdx.x, h = blockIdx.y, b = blockIdx.z;
    const int t = threadIdx.x;
    const int m0 = b * SEQ + c * CHUNK;

    if (t < CHUNK) dts[t] = g_dt[(size_t)(m0 + t) * NHEADS + h];
    #pragma unroll
    for (int i = 0; i < 4; i++) {
        int idx = t + i * 256;                 // 1024 entries
        int s = idx >> 4, n = idx & 15;
        Bsh[s][n] = g_xBC[(size_t)(m0 + s) * CONV_DIM + D_INNER + n];
        Csh[s][n] = g_xBC[(size_t)(m0 + s) * CONV_DIM + D_INNER + D_STATE + n];
    }
    __syncthreads();
    #pragma unroll
    for (int i = 0; i < 16; i++) {
        int idx = t + i * 256;                 // 4096 entries
        int s = idx >> 6, p = idx & 63;
        xs[s][p] = g_xBC[(size_t)(m0 + s) * CONV_DIM + h * HEADDIM + p] * dts[s];
    }
    __syncthreads();

    if (t == 0) {
        float Ah = -expf(A_log[h]);
        float run = 0.f;
        for (int s = 0; s < CHUNK; s++) { run += Ah * dts[s]; Acum[s] = run; }
    }
    __syncthreads();
    float Alast = Acum[CHUNK - 1];
    if (t < CHUNK) {
        decay[t] = expf(Alast - Acum[t]);
        g_Acum[(((size_t)(b * NCHUNK) + c) * NHEADS + h) * CHUNK + t] = Acum[t];
    }
    __syncthreads();

    // G[l][s] = (C[l]·B[s]) * exp(Acum[l]-Acum[s]),  s <= l
    #pragma unroll
    for (int i = 0; i < 16; i++) {
        int idx = t + i * 256;
        int l = idx >> 6, s = idx & 63;
        float g = 0.f;
        if (s <= l) {
            float d = 0.f;
            #pragma unroll
            for (int n = 0; n < D_STATE; n++) d += Csh[l][n] * Bsh[s][n];
            g = d * expf(Acum[l] - Acum[s]);
        }
        Gs[l][s] = g;
    }
    __syncthreads();

    // Y_diag = G @ x   (4x4 register micro-tile per thread)
    {
        const int p0 = (t & 15) * 4;
        const int l0 = (t >> 4) * 4;
        float acc[4][4];
        #pragma unroll
        for (int i = 0; i < 4; i++)
            #pragma unroll
            for (int j = 0; j < 4; j++) acc[i][j] = 0.f;
        for (int s = 0; s < CHUNK; s++) {
            float xv[4], gv[4];
            #pragma unroll
            for (int j = 0; j < 4; j++) xv[j] = xs[s][p0 + j];
            #pragma unroll
            for (int i = 0; i < 4; i++) gv[i] = Gs[l0 + i][s];
            #pragma unroll
            for (int i = 0; i < 4; i++)
                #pragma unroll
                for (int j = 0; j < 4; j++) acc[i][j] += gv[i] * xv[j];
        }
        #pragma unroll
        for (int i = 0; i < 4; i++)
            #pragma unroll
            for (int j = 0; j < 4; j++)
                g_y[(size_t)(m0 + l0 + i) * D_INNER + h * HEADDIM + p0 + j] = acc[i][j];
    }

    // chunk_states[p][n] = sum_s B[s,n] * decay[s] * x[s,p]
    {
        const int p  = t & 63;
        const int nb = (t >> 6) * 4;
        float acc[4] = {0.f, 0.f, 0.f, 0.f};
        for (int s = 0; s < CHUNK; s++) {
            float xv = xs[s][p] * decay[s];
            #pragma unroll
            for (int j = 0; j < 4; j++) acc[j] += Bsh[s][nb + j] * xv;
        }
        size_t base = ((((size_t)(b * NCHUNK) + c) * NHEADS + h) * HEADDIM + p) * D_STATE + nb;
        #pragma unroll
        for (int j = 0; j < 4; j++) g_cs[base + j] = acc[j];
    }
}

// ---------------- SSD stage 2: sequential cross-chunk state scan ------------
__global__ __launch_bounds__(1024) void ssd_scan_kernel()
{
    const int bh = blockIdx.x;                  // b*NHEADS + h
    const int b = bh / NHEADS, h = bh % NHEADS;
    const int t = threadIdx.x;                  // 1024 = HEADDIM*D_STATE
    float state = 0.f;
    for (int c = 0; c < NCHUNK; c++) {
        size_t base = (((size_t)(b * NCHUNK) + c) * NHEADS + h) * (HEADDIM * D_STATE);
        g_sp[base + t] = state;                 // state BEFORE this chunk
        float dA = expf(g_Acum[(((size_t)(b * NCHUNK) + c) * NHEADS + h) * CHUNK + (CHUNK - 1)]);
        state = state * dA + g_cs[base + t];
    }
}

// ---------------- SSD stage 3: off-diag + D*x + gate(silu(z)) ---------------
__global__ __launch_bounds__(256) void ssd_offdiag_kernel(const float* __restrict__ Dp)
{
    __shared__ float sp[CHUNK][D_STATE];      // indexed [p][n]
    __shared__ float Csh[CHUNK][D_STATE];
    __shared__ float eA[CHUNK];

    const int c = blockIdx.x, h = blockIdx.y, b = blockIdx.z;
    const int t = threadIdx.x;
    const int m0 = b * SEQ + c * CHUNK;
    size_t spbase = (((size_t)(b * NCHUNK) + c) * NHEADS + h) * (HEADDIM * D_STATE);

    #pragma unroll
    for (int i = 0; i < 4; i++) {
        int idx = t + i * 256;
        ((float*)sp)[idx] = g_sp[spbase + idx];
        int s = idx >> 4, n = idx & 15;
        Csh[s][n] = g_xBC[(size_t)(m0 + s) * CONV_DIM + D_INNER + D_STATE + n];
    }
    if (t < CHUNK)
        eA[t] = expf(g_Acum[(((size_t)(b * NCHUNK) + c) * NHEADS + h) * CHUNK + t]);
    __syncthreads();

    const float Dh = Dp[h];
    const int p = t & 63;
    const int lbase = (t >> 6) * 16;

    float spr[D_STATE];
    #pragma unroll
    for (int n = 0; n < D_STATE; n++) spr[n] = sp[p][n];

    for (int i = 0; i < 16; i++) {
        int l = lbase + i;
        int m = m0 + l;
        float d = 0.f;
        #pragma unroll
        for (int n = 0; n < D_STATE; n++) d += Csh[l][n] * spr[n];
        size_t yi = (size_t)m * D_INNER + h * HEADDIM + p;
        float yv = g_y[yi] + eA[l] * d;
        yv += Dh * g_xBC[(size_t)m * CONV_DIM + h * HEADDIM + p];
        float z = g_zxbcdt[(size_t)m * D_IN_PROJ + h * HEADDIM + p];
        yv *= z / (1.f + expf(-z));              // * silu(z)
        g_y[yi] = yv;
    }
}

// ---------------- RMSNorm over D_INNER, in-place ----------------------------
__global__ __launch_bounds__(256) void rmsnorm_kernel(const float* __restrict__ norm_w)
{
    const int m = blockIdx.x;
    const int t = threadIdx.x;
    size_t base = (size_t)m * D_INNER;
    float s = 0.f;
    for (int i = t; i < D_INNER; i += 256) {
        float v = g_y[base + i];
        s += v * v;
    }
    __shared__ float red[256];
    red[t] = s; __syncthreads();
    for (int o = 128; o > 0; o >>= 1) {
        if (t < o) red[t] += red[t + o];
        __syncthreads();
    }
    float scale = rsqrtf(red[0] / (float)D_INNER + 1e-5f);
    for (int i = t; i < D_INNER; i += 256)
        g_y[base + i] = g_y[base + i] * scale * norm_w[i];
}

// ---------------- launch ----------------------------------------------------
extern "C" void kernel_launch(void* const* d_in, const int* in_sizes, int n_in,
                              void* d_out, int out_size)
{
    const float* u       = (const float*)d_in[0];
    const float* W_in    = (const float*)d_in[1];
    const float* conv_w  = (const float*)d_in[2];
    const float* conv_b  = (const float*)d_in[3];
    const float* dt_bias = (const float*)d_in[4];
    const float* A_log   = (const float*)d_in[5];
    const float* Dp      = (const float*)d_in[6];
    const float* norm_w  = (const float*)d_in[7];
    const float* W_out   = (const float*)d_in[8];
    float* out = (float*)d_out;

    float *zx, *yv;
    cudaGetSymbolAddress((void**)&zx, g_zxbcdt);
    cudaGetSymbolAddress((void**)&yv, g_y);

    // 1. in_proj:  zxbcdt = u @ W_in^T   (8192 x 4160 x 1024)
    sgemm_nt<<<dim3((D_IN_PROJ + 127) / 128, MTOT / 128), 256>>>(
        u, W_in, zx, MTOT, D_IN_PROJ, D_MODEL);

    // 2. depthwise conv + silu on xBC slice
    conv_silu_kernel<<<(MTOT * CONV_DIM + 255) / 256, 256>>>(conv_w, conv_b);

    // 3. dt = softplus(raw + bias)
    dt_kernel<<<(MTOT * NHEADS + 255) / 256, 256>>>(dt_bias);

    // 4. SSD intra-chunk (Y_diag + chunk states)
    ssd_chunk_kernel<<<dim3(NCHUNK, NHEADS, BATCH), 256>>>(A_log);

    // 5. sequential cross-chunk scan
    ssd_scan_kernel<<<BATCH * NHEADS, 1024>>>();

    // 6. off-diagonal contribution + D*x + gating
    ssd_offdiag_kernel<<<dim3(NCHUNK, NHEADS, BATCH), 256>>>(Dp);

    // 7. RMSNorm
    rmsnorm_kernel<<<MTOT, 256>>>(norm_w);

    // 8. out_proj: out = y @ W_out^T   (8192 x 1024 x 2048)
    sgemm_nt<<<dim3(D_MODEL / 128, MTOT / 128), 256>>>(
        yv, W_out, out, MTOT, D_MODEL, D_INNER);
}

// round 3
// speedup vs baseline: 1.8635x; 1.8635x over previous
#include <cuda_runtime.h>
#include <math.h>
#include <stdint.h>

#define D_MODEL   1024
#define D_STATE   16
#define D_CONV    4
#define HEADDIM   64
#define CHUNK     64
#define D_INNER   2048
#define NHEADS    32
#define CONV_DIM  2080          // D_INNER + 2*D_STATE
#define D_IN_PROJ 4160          // 2*D_INNER + 2*D_STATE + NHEADS
#define BATCH     2
#define SEQ       4096
#define NCHUNK    (SEQ / CHUNK) // 64
#define MTOT      (BATCH * SEQ) // 8192

// ---------------- scratch (device globals; no allocation allowed) -----------
__device__ float g_zxbcdt[(size_t)MTOT * D_IN_PROJ];           // 136 MB
__device__ float g_xBC[(size_t)MTOT * CONV_DIM];               // 68 MB (post conv+silu)
__device__ float g_dt[(size_t)MTOT * NHEADS];                  // softplus(dt)
__device__ float g_Acum[(size_t)BATCH * NCHUNK * NHEADS * CHUNK];
__device__ float g_cs[(size_t)BATCH * NCHUNK * NHEADS * HEADDIM * D_STATE]; // chunk states
__device__ float g_sp[(size_t)BATCH * NCHUNK * NHEADS * HEADDIM * D_STATE]; // prefix states
__device__ float g_y[(size_t)MTOT * D_INNER];                  // 64 MB

// ============================================================================
// TF32 tensor-core GEMM: C[M,N] = A[M,K] @ B[N,K]^T
// 128x128x16 block tile, 256 threads, 8 warps (2 along M x 4 along N),
// warp tile 64x32 -> 4x4 grid of m16n8k8 MMAs per k8 step.
// Inputs converted fp32 -> tf32 with round-to-nearest in the smem-fill path.
// ============================================================================
#define GBM 128
#define GBN 128
#define GBK 16
#define GPAD 4
#define GLDK (GBK + GPAD)   // 20

__device__ __forceinline__ uint32_t f2tf32(float x) {
    uint32_t r;
    asm("cvt.rna.tf32.f32 %0, %1;" : "=r"(r) : "f"(x));
    return r;
}

__global__ __launch_bounds__(256, 1) void tf32gemm_nt(
    const float* __restrict__ A, const float* __restrict__ B,
    float* __restrict__ C, int M, int N, int K)
{
    __shared__ uint32_t As[2][GBM * GLDK];
    __shared__ uint32_t Bs[2][GBN * GLDK];

    const int tid  = threadIdx.x;
    const int wid  = tid >> 5;
    const int lane = tid & 31;
    const int qr   = lane >> 2;   // 0..7
    const int qc   = lane & 3;    // 0..3
    const int wm   = (wid & 1) * 64;   // warp M offset
    const int wn   = (wid >> 1) * 32;  // warp N offset

    const int brow = blockIdx.y * GBM;
    const int bcol = blockIdx.x * GBN;

    // global load assignment: each thread loads 8 floats of A and 8 of B
    const int lr  = tid >> 1;          // 0..127 row within tile
    const int lk  = (tid & 1) * 8;     // 0 or 8 k offset
    const float* Ab = A + (size_t)(brow + lr) * K + lk;
    const int bn_row = bcol + lr;
    const float* Bb = (bn_row < N) ? (B + (size_t)bn_row * K + lk) : A; // dummy ptr if OOB
    const bool bvalid = (bn_row < N);

    float acc[4][4][4];
    #pragma unroll
    for (int mi = 0; mi < 4; mi++)
        #pragma unroll
        for (int ni = 0; ni < 4; ni++)
            #pragma unroll
            for (int r = 0; r < 4; r++) acc[mi][ni][r] = 0.f;

    const int KT = K / GBK;
    float4 pa0, pa1, pb0, pb1;

    // prologue: load tile 0
    pa0 = *(const float4*)(Ab);
    pa1 = *(const float4*)(Ab + 4);
    if (bvalid) { pb0 = *(const float4*)(Bb); pb1 = *(const float4*)(Bb + 4); }
    else        { pb0 = pb1 = make_float4(0.f,0.f,0.f,0.f); }
    {
        uint32_t* da = &As[0][lr * GLDK + lk];
        da[0]=f2tf32(pa0.x); da[1]=f2tf32(pa0.y); da[2]=f2tf32(pa0.z); da[3]=f2tf32(pa0.w);
        da[4]=f2tf32(pa1.x); da[5]=f2tf32(pa1.y); da[6]=f2tf32(pa1.z); da[7]=f2tf32(pa1.w);
        uint32_t* db = &Bs[0][lr * GLDK + lk];
        db[0]=f2tf32(pb0.x); db[1]=f2tf32(pb0.y); db[2]=f2tf32(pb0.z); db[3]=f2tf32(pb0.w);
        db[4]=f2tf32(pb1.x); db[5]=f2tf32(pb1.y); db[6]=f2tf32(pb1.z); db[7]=f2tf32(pb1.w);
    }
    __syncthreads();

    for (int kt = 0; kt < KT; kt++) {
        const int cur = kt & 1;
        // prefetch next tile to registers (LDG latency hidden by MMAs below)
        if (kt + 1 < KT) {
            const float* Ap = Ab + (size_t)(kt + 1) * GBK;
            pa0 = *(const float4*)(Ap);
            pa1 = *(const float4*)(Ap + 4);
            if (bvalid) {
                const float* Bp = Bb + (size_t)(kt + 1) * GBK;
                pb0 = *(const float4*)(Bp); pb1 = *(const float4*)(Bp + 4);
            }
        }

        const uint32_t* Asb = As[cur];
        const uint32_t* Bsb = Bs[cur];
        #pragma unroll
        for (int k0 = 0; k0 < GBK; k0 += 8) {
            uint32_t af[4][4], bf[4][2];
            #pragma unroll
            for (int mi = 0; mi < 4; mi++) {
                int r0 = wm + mi * 16 + qr;
                af[mi][0] = Asb[(r0)     * GLDK + k0 + qc];
                af[mi][1] = Asb[(r0 + 8) * GLDK + k0 + qc];
                af[mi][2] = Asb[(r0)     * GLDK + k0 + qc + 4];
                af[mi][3] = Asb[(r0 + 8) * GLDK + k0 + qc + 4];
            }
            #pragma unroll
            for (int ni = 0; ni < 4; ni++) {
                int n0 = wn + ni * 8 + qr;
                bf[ni][0] = Bsb[n0 * GLDK + k0 + qc];
                bf[ni][1] = Bsb[n0 * GLDK + k0 + qc + 4];
            }
            #pragma unroll
            for (int mi = 0; mi < 4; mi++)
                #pragma unroll
                for (int ni = 0; ni < 4; ni++) {
                    asm volatile(
                        "mma.sync.aligned.m16n8k8.row.col.f32.tf32.tf32.f32 "
                        "{%0,%1,%2,%3}, {%4,%5,%6,%7}, {%8,%9}, {%0,%1,%2,%3};"
                        : "+f"(acc[mi][ni][0]), "+f"(acc[mi][ni][1]),
                          "+f"(acc[mi][ni][2]), "+f"(acc[mi][ni][3])
                        : "r"(af[mi][0]), "r"(af[mi][1]), "r"(af[mi][2]), "r"(af[mi][3]),
                          "r"(bf[ni][0]), "r"(bf[ni][1]));
                }
        }

        if (kt + 1 < KT) {
            // write next tile into the other buffer (its readers finished at kt-1)
            const int nxt = cur ^ 1;
            uint32_t* da = &As[nxt][lr * GLDK + lk];
            da[0]=f2tf32(pa0.x); da[1]=f2tf32(pa0.y); da[2]=f2tf32(pa0.z); da[3]=f2tf32(pa0.w);
            da[4]=f2tf32(pa1.x); da[5]=f2tf32(pa1.y); da[6]=f2tf32(pa1.z); da[7]=f2tf32(pa1.w);
            uint32_t* db = &Bs[nxt][lr * GLDK + lk];
            if (bvalid) {
                db[0]=f2tf32(pb0.x); db[1]=f2tf32(pb0.y); db[2]=f2tf32(pb0.z); db[3]=f2tf32(pb0.w);
                db[4]=f2tf32(pb1.x); db[5]=f2tf32(pb1.y); db[6]=f2tf32(pb1.z); db[7]=f2tf32(pb1.w);
            } else {
                db[0]=db[1]=db[2]=db[3]=db[4]=db[5]=db[6]=db[7]=0u;
            }
            __syncthreads();
        }
    }

    // epilogue
    #pragma unroll
    for (int mi = 0; mi < 4; mi++) {
        int row0 = brow + wm + mi * 16 + qr;
        #pragma unroll
        for (int ni = 0; ni < 4; ni++) {
            int col = bcol + wn + ni * 8 + qc * 2;
            if (col < N) {
                C[(size_t)row0 * N + col]       = acc[mi][ni][0];
                C[(size_t)(row0+8) * N + col]   = acc[mi][ni][2];
            }
            if (col + 1 < N) {
                C[(size_t)row0 * N + col + 1]     = acc[mi][ni][1];
                C[(size_t)(row0+8) * N + col + 1] = acc[mi][ni][3];
            }
        }
    }
}

// ---------------- depthwise causal conv(4) + bias + SiLU --------------------
__global__ void conv_silu_kernel(const float* __restrict__ conv_w,
                                 const float* __restrict__ conv_b)
{
    int idx = blockIdx.x * blockDim.x + threadIdx.x;
    if (idx >= MTOT * CONV_DIM) return;
    int c = idx % CONV_DIM;
    int m = idx / CONV_DIM;          // b*SEQ + l
    int l = m & (SEQ - 1);

    float acc = conv_b[c];
    #pragma unroll
    for (int j = 0; j < D_CONV; j++) {
        int lj = l - (D_CONV - 1) + j;
        if (lj >= 0)
            acc += conv_w[c * D_CONV + j] *
                   g_zxbcdt[(size_t)(m - (D_CONV - 1) + j) * D_IN_PROJ + D_INNER + c];
    }
    g_xBC[idx] = acc / (1.f + expf(-acc));   // silu
}

// ---------------- dt = softplus(raw + bias) ---------------------------------
__global__ void dt_kernel(const float* __restrict__ dt_bias)
{
    int idx = blockIdx.x * blockDim.x + threadIdx.x;
    if (idx >= MTOT * NHEADS) return;
    int h = idx & (NHEADS - 1);
    int m = idx >> 5;
    float x = g_zxbcdt[(size_t)m * D_IN_PROJ + (D_IN_PROJ - NHEADS) + h] + dt_bias[h];
    g_dt[idx] = (x > 20.f) ? x : log1pf(expf(x));
}

// ---------------- SSD stage 1: per-chunk diag output + chunk states ---------
__global__ __launch_bounds__(256) void ssd_chunk_kernel(const float* __restrict__ A_log)
{
    __shared__ float xs[CHUNK][HEADDIM];     // x * dt
    __shared__ float Gs[CHUNK][CHUNK];
    __shared__ float Bsh[CHUNK][D_STATE];
    __shared__ float Csh[CHUNK][D_STATE];
    __shared__ float Acum[CHUNK];
    __shared__ float dts[CHUNK];
    __shared__ float decay[CHUNK];

    const int c = blockIdx.x, h = blockIdx.y, b = blockIdx.z;
    const int t = threadIdx.x;
    const int m0 = b * SEQ + c * CHUNK;

    if (t < CHUNK) dts[t] = g_dt[(size_t)(m0 + t) * NHEADS + h];
    #pragma unroll
    for (int i = 0; i < 4; i++) {
        int idx = t + i * 256;                 // 1024 entries
        int s = idx >> 4, n = idx & 15;
        Bsh[s][n] = g_xBC[(size_t)(m0 + s) * CONV_DIM + D_INNER + n];
        Csh[s][n] = g_xBC[(size_t)(m0 + s) * CONV_DIM + D_INNER + D_STATE + n];
    }
    __syncthreads();
    #pragma unroll
    for (int i = 0; i < 16; i++) {
        int idx = t + i * 256;                 // 4096 entries
        int s = idx >> 6, p = idx & 63;
        xs[s][p] = g_xBC[(size_t)(m0 + s) * CONV_DIM + h * HEADDIM + p] * dts[s];
    }
    __syncthreads();

    if (t == 0) {
        float Ah = -expf(A_log[h]);
        float run = 0.f;
        for (int s = 0; s < CHUNK; s++) { run += Ah * dts[s]; Acum[s] = run; }
    }
    __syncthreads();
    float Alast = Acum[CHUNK - 1];
    if (t < CHUNK) {
        decay[t] = expf(Alast - Acum[t]);
        g_Acum[(((size_t)(b * NCHUNK) + c) * NHEADS + h) * CHUNK + t] = Acum[t];
    }
    __syncthreads();

    // G[l][s] = (C[l]·B[s]) * exp(Acum[l]-Acum[s]),  s <= l
    #pragma unroll
    for (int i = 0; i < 16; i++) {
        int idx = t + i * 256;
        int l = idx >> 6, s = idx & 63;
        float g = 0.f;
        if (s <= l) {
            float d = 0.f;
            #pragma unroll
            for (int n = 0; n < D_STATE; n++) d += Csh[l][n] * Bsh[s][n];
            g = d * expf(Acum[l] - Acum[s]);
        }
        Gs[l][s] = g;
    }
    __syncthreads();

    // Y_diag = G @ x   (4x4 register micro-tile per thread)
    {
        const int p0 = (t & 15) * 4;
        const int l0 = (t >> 4) * 4;
        float acc[4][4];
        #pragma unroll
        for (int i = 0; i < 4; i++)
            #pragma unroll
            for (int j = 0; j < 4; j++) acc[i][j] = 0.f;
        for (int s = 0; s < CHUNK; s++) {
            float xv[4], gv[4];
            #pragma unroll
            for (int j = 0; j < 4; j++) xv[j] = xs[s][p0 + j];
            #pragma unroll
            for (int i = 0; i < 4; i++) gv[i] = Gs[l0 + i][s];
            #pragma unroll
            for (int i = 0; i < 4; i++)
                #pragma unroll
                for (int j = 0; j < 4; j++) acc[i][j] += gv[i] * xv[j];
        }
        #pragma unroll
        for (int i = 0; i < 4; i++)
            #pragma unroll
            for (int j = 0; j < 4; j++)
                g_y[(size_t)(m0 + l0 + i) * D_INNER + h * HEADDIM + p0 + j] = acc[i][j];
    }

    // chunk_states[p][n] = sum_s B[s,n] * decay[s] * x[s,p]
    {
        const int p  = t & 63;
        const int nb = (t >> 6) * 4;
        float acc[4] = {0.f, 0.f, 0.f, 0.f};
        for (int s = 0; s < CHUNK; s++) {
            float xv = xs[s][p] * decay[s];
            #pragma unroll
            for (int j = 0; j < 4; j++) acc[j] += Bsh[s][nb + j] * xv;
        }
        size_t base = ((((size_t)(b * NCHUNK) + c) * NHEADS + h) * HEADDIM + p) * D_STATE + nb;
        #pragma unroll
        for (int j = 0; j < 4; j++) g_cs[base + j] = acc[j];
    }
}

// ---------------- SSD stage 2: sequential cross-chunk state scan ------------
__global__ __launch_bounds__(1024) void ssd_scan_kernel()
{
    const int bh = blockIdx.x;                  // b*NHEADS + h
    const int b = bh / NHEADS, h = bh % NHEADS;
    const int t = threadIdx.x;                  // 1024 = HEADDIM*D_STATE
    float state = 0.f;
    for (int c = 0; c < NCHUNK; c++) {
        size_t base = (((size_t)(b * NCHUNK) + c) * NHEADS + h) * (HEADDIM * D_STATE);
        g_sp[base + t] = state;                 // state BEFORE this chunk
        float dA = expf(g_Acum[(((size_t)(b * NCHUNK) + c) * NHEADS + h) * CHUNK + (CHUNK - 1)]);
        state = state * dA + g_cs[base + t];
    }
}

// ---------------- SSD stage 3: off-diag + D*x + gate(silu(z)) ---------------
__global__ __launch_bounds__(256) void ssd_offdiag_kernel(const float* __restrict__ Dp)
{
    __shared__ float sp[CHUNK][D_STATE];      // indexed [p][n]
    __shared__ float Csh[CHUNK][D_STATE];
    __shared__ float eA[CHUNK];

    const int c = blockIdx.x, h = blockIdx.y, b = blockIdx.z;
    const int t = threadIdx.x;
    const int m0 = b * SEQ + c * CHUNK;
    size_t spbase = (((size_t)(b * NCHUNK) + c) * NHEADS + h) * (HEADDIM * D_STATE);

    #pragma unroll
    for (int i = 0; i < 4; i++) {
        int idx = t + i * 256;
        ((float*)sp)[idx] = g_sp[spbase + idx];
        int s = idx >> 4, n = idx & 15;
        Csh[s][n] = g_xBC[(size_t)(m0 + s) * CONV_DIM + D_INNER + D_STATE + n];
    }
    if (t < CHUNK)
        eA[t] = expf(g_Acum[(((size_t)(b * NCHUNK) + c) * NHEADS + h) * CHUNK + t]);
    __syncthreads();

    const float Dh = Dp[h];
    const int p = t & 63;
    const int lbase = (t >> 6) * 16;

    float spr[D_STATE];
    #pragma unroll
    for (int n = 0; n < D_STATE; n++) spr[n] = sp[p][n];

    for (int i = 0; i < 16; i++) {
        int l = lbase + i;
        int m = m0 + l;
        float d = 0.f;
        #pragma unroll
        for (int n = 0; n < D_STATE; n++) d += Csh[l][n] * spr[n];
        size_t yi = (size_t)m * D_INNER + h * HEADDIM + p;
        float yv = g_y[yi] + eA[l] * d;
        yv += Dh * g_xBC[(size_t)m * CONV_DIM + h * HEADDIM + p];
        float z = g_zxbcdt[(size_t)m * D_IN_PROJ + h * HEADDIM + p];
        yv *= z / (1.f + expf(-z));              // * silu(z)
        g_y[yi] = yv;
    }
}

// ---------------- RMSNorm over D_INNER, in-place ----------------------------
__global__ __launch_bounds__(256) void rmsnorm_kernel(const float* __restrict__ norm_w)
{
    const int m = blockIdx.x;
    const int t = threadIdx.x;
    size_t base = (size_t)m * D_INNER;
    float s = 0.f;
    for (int i = t; i < D_INNER; i += 256) {
        float v = g_y[base + i];
        s += v * v;
    }
    __shared__ float red[256];
    red[t] = s; __syncthreads();
    for (int o = 128; o > 0; o >>= 1) {
        if (t < o) red[t] += red[t + o];
        __syncthreads();
    }
    float scale = rsqrtf(red[0] / (float)D_INNER + 1e-5f);
    for (int i = t; i < D_INNER; i += 256)
        g_y[base + i] = g_y[base + i] * scale * norm_w[i];
}

// ---------------- launch ----------------------------------------------------
extern "C" void kernel_launch(void* const* d_in, const int* in_sizes, int n_in,
                              void* d_out, int out_size)
{
    const float* u       = (const float*)d_in[0];
    const float* W_in    = (const float*)d_in[1];
    const float* conv_w  = (const float*)d_in[2];
    const float* conv_b  = (const float*)d_in[3];
    const float* dt_bias = (const float*)d_in[4];
    const float* A_log   = (const float*)d_in[5];
    const float* Dp      = (const float*)d_in[6];
    const float* norm_w  = (const float*)d_in[7];
    const float* W_out   = (const float*)d_in[8];
    float* out = (float*)d_out;

    float *zx, *yv;
    cudaGetSymbolAddress((void**)&zx, g_zxbcdt);
    cudaGetSymbolAddress((void**)&yv, g_y);

    // 1. in_proj:  zxbcdt = u @ W_in^T   (8192 x 4160 x 1024) -- TF32 MMA
    tf32gemm_nt<<<dim3((D_IN_PROJ + GBN - 1) / GBN, MTOT / GBM), 256>>>(
        u, W_in, zx, MTOT, D_IN_PROJ, D_MODEL);

    // 2. depthwise conv + silu on xBC slice
    conv_silu_kernel<<<(MTOT * CONV_DIM + 255) / 256, 256>>>(conv_w, conv_b);

    // 3. dt = softplus(raw + bias)
    dt_kernel<<<(MTOT * NHEADS + 255) / 256, 256>>>(dt_bias);

    // 4. SSD intra-chunk (Y_diag + chunk states)
    ssd_chunk_kernel<<<dim3(NCHUNK, NHEADS, BATCH), 256>>>(A_log);

    // 5. sequential cross-chunk scan
    ssd_scan_kernel<<<BATCH * NHEADS, 1024>>>();

    // 6. off-diagonal contribution + D*x + gating
    ssd_offdiag_kernel<<<dim3(NCHUNK, NHEADS, BATCH), 256>>>(Dp);

    // 7. RMSNorm
    rmsnorm_kernel<<<MTOT, 256>>>(norm_w);

    // 8. out_proj: out = y @ W_out^T   (8192 x 1024 x 2048) -- TF32 MMA
    tf32gemm_nt<<<dim3(D_MODEL / GBN, MTOT / GBM), 256>>>(
        yv, W_out, out, MTOT, D_MODEL, D_INNER);
}

// round 5
// speedup vs baseline: 2.3857x; 1.2803x over previous
#include <cuda_runtime.h>
#include <cuda_bf16.h>
#include <math.h>
#include <stdint.h>

#define D_MODEL   1024
#define D_STATE   16
#define D_CONV    4
#define HEADDIM   64
#define CHUNK     64
#define D_INNER   2048
#define NHEADS    32
#define CONV_DIM  2080          // D_INNER + 2*D_STATE
#define D_IN_PROJ 4160          // 2*D_INNER + 2*D_STATE + NHEADS
#define BATCH     2
#define SEQ       4096
#define NCHUNK    (SEQ / CHUNK) // 64
#define MTOT      (BATCH * SEQ) // 8192

// ---------------- scratch (device globals; no allocation allowed) -----------
__device__ float g_zxbcdt[(size_t)MTOT * D_IN_PROJ];
__device__ float g_xBC[(size_t)MTOT * CONV_DIM];
__device__ float g_dt[(size_t)MTOT * NHEADS];
__device__ float g_Acum[(size_t)BATCH * NCHUNK * NHEADS * CHUNK];
__device__ float g_cs[(size_t)BATCH * NCHUNK * NHEADS * HEADDIM * D_STATE];
__device__ float g_sp[(size_t)BATCH * NCHUNK * NHEADS * HEADDIM * D_STATE];
__device__ float g_y[(size_t)MTOT * D_INNER];

// bf16 hi/lo split buffers (stored as u16 to keep trivial init)
__device__ unsigned short g_uhi[(size_t)MTOT * D_MODEL];
__device__ unsigned short g_ulo[(size_t)MTOT * D_MODEL];
__device__ unsigned short g_w1hi[(size_t)D_IN_PROJ * D_MODEL];
__device__ unsigned short g_w1lo[(size_t)D_IN_PROJ * D_MODEL];
__device__ unsigned short g_yhi[(size_t)MTOT * D_INNER];
__device__ unsigned short g_ylo[(size_t)MTOT * D_INNER];
__device__ unsigned short g_w2hi[(size_t)D_MODEL * D_INNER];
__device__ unsigned short g_w2lo[(size_t)D_MODEL * D_INNER];

// ============================================================================
// helpers
// ============================================================================
__device__ __forceinline__ uint32_t cvta_s(const void* p) {
    uint32_t a;
    asm("{ .reg .u64 t; cvta.to.shared.u64 t, %1; cvt.u32.u64 %0, t; }" : "=r"(a) : "l"(p));
    return a;
}
__device__ __forceinline__ void cpa16(uint32_t dst, const void* src, int sz) {
    asm volatile("cp.async.cg.shared.global [%0], [%1], 16, %2;"
                 :: "r"(dst), "l"(src), "r"(sz));
}
#define CP_COMMIT() asm volatile("cp.async.commit_group;" ::: "memory")
#define CP_WAIT2()  asm volatile("cp.async.wait_group 2;" ::: "memory")

__device__ __forceinline__ void ldm_x4(uint32_t& r0, uint32_t& r1, uint32_t& r2,
                                       uint32_t& r3, uint32_t addr) {
    asm volatile("ldmatrix.sync.aligned.m8n8.x4.shared.b16 {%0,%1,%2,%3}, [%4];"
                 : "=r"(r0), "=r"(r1), "=r"(r2), "=r"(r3) : "r"(addr));
}
__device__ __forceinline__ void ldm_x2(uint32_t& r0, uint32_t& r1, uint32_t addr) {
    asm volatile("ldmatrix.sync.aligned.m8n8.x2.shared.b16 {%0,%1}, [%2];"
                 : "=r"(r0), "=r"(r1) : "r"(addr));
}
__device__ __forceinline__ void mma_bf16(float* d, const uint32_t* a, const uint32_t* b) {
    asm volatile(
        "mma.sync.aligned.m16n8k16.row.col.f32.bf16.bf16.f32 "
        "{%0,%1,%2,%3},{%4,%5,%6,%7},{%8,%9},{%0,%1,%2,%3};"
        : "+f"(d[0]), "+f"(d[1]), "+f"(d[2]), "+f"(d[3])
        : "r"(a[0]), "r"(a[1]), "r"(a[2]), "r"(a[3]), "r"(b[0]), "r"(b[1]));
}

// ============================================================================
// bf16 3-term split GEMM: C[M,N] = A[M,K] @ B[N,K]^T (fp32 accuracy ~1e-5)
// Terms along K: [Ahi*Bhi | Ahi*Blo | Alo*Bhi]. 128x128 tile, BK=64,
// 4-stage cp.async pipeline, ldmatrix fragments, 256 threads (8 warps 2x4).
// ============================================================================
#define BM 128
#define BN 128
#define BKG 64
#define STG 4
#define ATILE (BM * BKG * 2)       // 16384 B
#define BTILE (BN * BKG * 2)       // 16384 B
#define STGB (ATILE + BTILE)       // 32768 B
#define GSMEM (STG * STGB)         // 131072 B

__global__ __launch_bounds__(256, 1) void bf16gemm3(
    const unsigned short* __restrict__ Ahi, const unsigned short* __restrict__ Alo,
    const unsigned short* __restrict__ Bhi, const unsigned short* __restrict__ Blo,
    float* __restrict__ C, int M, int N, int K)
{
    extern __shared__ char smraw[];
    const uint32_t smb = cvta_s(smraw);
    const int tid = threadIdx.x, lane = tid & 31, wid = tid >> 5;
    const int wm = (wid & 1) * 64, wn = (wid >> 1) * 32;
    const int qr = lane >> 2, qc = lane & 3;
    const int brow = blockIdx.y * BM, bcol = blockIdx.x * BN;
    const int KBblk = K >> 6, KBt = 3 * KBblk;

    const int crow = tid >> 3;   // 0..31 (4 passes of 32 rows)
    const int cg   = tid & 7;    // 16B granule within 128B row

    float acc[4][4][4];
    #pragma unroll
    for (int mi = 0; mi < 4; mi++)
        #pragma unroll
        for (int ni = 0; ni < 4; ni++)
            #pragma unroll
            for (int r = 0; r < 4; r++) acc[mi][ni][r] = 0.f;

    auto issue = [&](int kb) {
        if (kb >= KBt) return;
        const unsigned short *pa, *pb; int kk;
        if (kb < KBblk)          { pa = Ahi; pb = Bhi; kk = kb; }
        else if (kb < 2 * KBblk) { pa = Ahi; pb = Blo; kk = kb - KBblk; }
        else                     { pa = Alo; pb = Bhi; kk = kb - 2 * KBblk; }
        const int st = kb & (STG - 1);
        const uint32_t abase = smb + st * STGB;
        const uint32_t bbase = abase + ATILE;
        #pragma unroll
        for (int p = 0; p < 4; p++) {
            int r = crow + p * 32;
            uint32_t ad = abase + r * 128 + ((cg ^ (r & 7)) * 16);
            cpa16(ad, pa + (size_t)(brow + r) * K + kk * BKG + cg * 8, 16);
            int bn = bcol + r;
            uint32_t bd = bbase + r * 128 + ((cg ^ (r & 7)) * 16);
            cpa16(bd, pb + (size_t)(bn < N ? bn : 0) * K + kk * BKG + cg * 8,
                  bn < N ? 16 : 0);
        }
    };

    issue(0); CP_COMMIT();
    issue(1); CP_COMMIT();
    issue(2); CP_COMMIT();

    for (int kb = 0; kb < KBt; kb++) {
        CP_WAIT2();
        __syncthreads();
        issue(kb + 3); CP_COMMIT();

        const int st = kb & (STG - 1);
        const uint32_t abase = smb + st * STGB;
        const uint32_t bbase = abase + ATILE;
        #pragma unroll
        for (int ks = 0; ks < 4; ks++) {
            uint32_t af[4][4], bfr[4][2];
            #pragma unroll
            for (int mi = 0; mi < 4; mi++) {
                int r = wm + mi * 16 + (lane & 15);
                int g = (ks * 2 + (lane >> 4)) ^ (r & 7);
                ldm_x4(af[mi][0], af[mi][1], af[mi][2], af[mi][3],
                       abase + r * 128 + g * 16);
            }
            #pragma unroll
            for (int ni = 0; ni < 4; ni++) {
                int r = wn + ni * 8 + (lane & 7);
                int g = (ks * 2 + ((lane >> 3) & 1)) ^ (r & 7);
                ldm_x2(bfr[ni][0], bfr[ni][1], bbase + r * 128 + g * 16);
            }
            #pragma unroll
            for (int mi = 0; mi < 4; mi++)
                #pragma unroll
                for (int ni = 0; ni < 4; ni++)
                    mma_bf16(acc[mi][ni], af[mi], bfr[ni]);
        }
    }

    // epilogue
    #pragma unroll
    for (int mi = 0; mi < 4; mi++) {
        int row0 = brow + wm + mi * 16 + qr;
        #pragma unroll
        for (int ni = 0; ni < 4; ni++) {
            int col = bcol + wn + ni * 8 + qc * 2;
            if (col < N) {
                float2 v0 = make_float2(acc[mi][ni][0], acc[mi][ni][1]);
                float2 v1 = make_float2(acc[mi][ni][2], acc[mi][ni][3]);
                *(float2*)(C + (size_t)row0 * N + col) = v0;
                *(float2*)(C + (size_t)(row0 + 8) * N + col) = v1;
            }
        }
    }
}

// ---------------- fp32 -> bf16 hi/lo split ----------------------------------
__global__ void split_kernel(const float* __restrict__ s,
                             unsigned short* __restrict__ hi,
                             unsigned short* __restrict__ lo, int n)
{
    int i = (blockIdx.x * 256 + threadIdx.x) * 4;
    if (i >= n) return;
    float4 v = *(const float4*)(s + i);
    __nv_bfloat16 h0 = __float2bfloat16_rn(v.x);
    __nv_bfloat16 h1 = __float2bfloat16_rn(v.y);
    __nv_bfloat16 h2 = __float2bfloat16_rn(v.z);
    __nv_bfloat16 h3 = __float2bfloat16_rn(v.w);
    __nv_bfloat16 l0 = __float2bfloat16_rn(v.x - __bfloat162float(h0));
    __nv_bfloat16 l1 = __float2bfloat16_rn(v.y - __bfloat162float(h1));
    __nv_bfloat16 l2 = __float2bfloat16_rn(v.z - __bfloat162float(h2));
    __nv_bfloat16 l3 = __float2bfloat16_rn(v.w - __bfloat162float(h3));
    ushort4 hv = make_ushort4(*(unsigned short*)&h0, *(unsigned short*)&h1,
                              *(unsigned short*)&h2, *(unsigned short*)&h3);
    ushort4 lv = make_ushort4(*(unsigned short*)&l0, *(unsigned short*)&l1,
                              *(unsigned short*)&l2, *(unsigned short*)&l3);
    *(ushort4*)(hi + i) = hv;
    *(ushort4*)(lo + i) = lv;
}

// ---------------- depthwise causal conv(4) + bias + SiLU --------------------
__global__ void conv_silu_kernel(const float* __restrict__ conv_w,
                                 const float* __restrict__ conv_b)
{
    int idx = blockIdx.x * blockDim.x + threadIdx.x;
    if (idx >= MTOT * CONV_DIM) return;
    int c = idx % CONV_DIM;
    int m = idx / CONV_DIM;
    int l = m & (SEQ - 1);

    float acc = conv_b[c];
    #pragma unroll
    for (int j = 0; j < D_CONV; j++) {
        int lj = l - (D_CONV - 1) + j;
        if (lj >= 0)
            acc += conv_w[c * D_CONV + j] *
                   g_zxbcdt[(size_t)(m - (D_CONV - 1) + j) * D_IN_PROJ + D_INNER + c];
    }
    g_xBC[idx] = acc / (1.f + expf(-acc));
}

// ---------------- dt = softplus(raw + bias) ---------------------------------
__global__ void dt_kernel(const float* __restrict__ dt_bias)
{
    int idx = blockIdx.x * blockDim.x + threadIdx.x;
    if (idx >= MTOT * NHEADS) return;
    int h = idx & (NHEADS - 1);
    int m = idx >> 5;
    float x = g_zxbcdt[(size_t)m * D_IN_PROJ + (D_IN_PROJ - NHEADS) + h] + dt_bias[h];
    g_dt[idx] = (x > 20.f) ? x : log1pf(expf(x));
}

// ---------------- SSD stage 1: per-chunk diag output + chunk states ---------
__global__ __launch_bounds__(256) void ssd_chunk_kernel(const float* __restrict__ A_log)
{
    __shared__ float xs[CHUNK][HEADDIM];
    __shared__ float Gs[CHUNK][CHUNK];
    __shared__ float Bsh[CHUNK][D_STATE];
    __shared__ float Csh[CHUNK][D_STATE];
    __shared__ float Acum[CHUNK];
    __shared__ float dts[CHUNK];
    __shared__ float decay[CHUNK];

    const int c = blockIdx.x, h = blockIdx.y, b = blockIdx.z;
    const int t = threadIdx.x;
    const int m0 = b * SEQ + c * CHUNK;

    if (t < CHUNK) dts[t] = g_dt[(size_t)(m0 + t) * NHEADS + h];
    #pragma unroll
    for (int i = 0; i < 4; i++) {
        int idx = t + i * 256;
        int s = idx >> 4, n = idx & 15;
        Bsh[s][n] = g_xBC[(size_t)(m0 + s) * CONV_DIM + D_INNER + n];
        Csh[s][n] = g_xBC[(size_t)(m0 + s) * CONV_DIM + D_INNER + D_STATE + n];
    }
    __syncthreads();
    #pragma unroll
    for (int i = 0; i < 16; i++) {
        int idx = t + i * 256;
        int s = idx >> 6, p = idx & 63;
        xs[s][p] = g_xBC[(size_t)(m0 + s) * CONV_DIM + h * HEADDIM + p] * dts[s];
    }
    __syncthreads();

    if (t == 0) {
        float Ah = -expf(A_log[h]);
        float run = 0.f;
        for (int s = 0; s < CHUNK; s++) { run += Ah * dts[s]; Acum[s] = run; }
    }
    __syncthreads();
    float Alast = Acum[CHUNK - 1];
    if (t < CHUNK) {
        decay[t] = expf(Alast - Acum[t]);
        g_Acum[(((size_t)(b * NCHUNK) + c) * NHEADS + h) * CHUNK + t] = Acum[t];
    }
    __syncthreads();

    #pragma unroll
    for (int i = 0; i < 16; i++) {
        int idx = t + i * 256;
        int l = idx >> 6, s = idx & 63;
        float g = 0.f;
        if (s <= l) {
            float d = 0.f;
            #pragma unroll
            for (int n = 0; n < D_STATE; n++) d += Csh[l][n] * Bsh[s][n];
            g = d * expf(Acum[l] - Acum[s]);
        }
        Gs[l][s] = g;
    }
    __syncthreads();

    {
        const int p0 = (t & 15) * 4;
        const int l0 = (t >> 4) * 4;
        float acc[4][4];
        #pragma unroll
        for (int i = 0; i < 4; i++)
            #pragma unroll
            for (int j = 0; j < 4; j++) acc[i][j] = 0.f;
        for (int s = 0; s < CHUNK; s++) {
            float xv[4], gv[4];
            #pragma unroll
            for (int j = 0; j < 4; j++) xv[j] = xs[s][p0 + j];
            #pragma unroll
            for (int i = 0; i < 4; i++) gv[i] = Gs[l0 + i][s];
            #pragma unroll
            for (int i = 0; i < 4; i++)
                #pragma unroll
                for (int j = 0; j < 4; j++) acc[i][j] += gv[i] * xv[j];
        }
        #pragma unroll
        for (int i = 0; i < 4; i++)
            #pragma unroll
            for (int j = 0; j < 4; j++)
                g_y[(size_t)(m0 + l0 + i) * D_INNER + h * HEADDIM + p0 + j] = acc[i][j];
    }

    {
        const int p  = t & 63;
        const int nb = (t >> 6) * 4;
        float acc[4] = {0.f, 0.f, 0.f, 0.f};
        for (int s = 0; s < CHUNK; s++) {
            float xv = xs[s][p] * decay[s];
            #pragma unroll
            for (int j = 0; j < 4; j++) acc[j] += Bsh[s][nb + j] * xv;
        }
        size_t base = ((((size_t)(b * NCHUNK) + c) * NHEADS + h) * HEADDIM + p) * D_STATE + nb;
        #pragma unroll
        for (int j = 0; j < 4; j++) g_cs[base + j] = acc[j];
    }
}

// ---------------- SSD stage 2: sequential cross-chunk state scan ------------
__global__ __launch_bounds__(1024) void ssd_scan_kernel()
{
    const int bh = blockIdx.x;
    const int b = bh / NHEADS, h = bh % NHEADS;
    const int t = threadIdx.x;
    float state = 0.f;
    for (int c = 0; c < NCHUNK; c++) {
        size_t base = (((size_t)(b * NCHUNK) + c) * NHEADS + h) * (HEADDIM * D_STATE);
        g_sp[base + t] = state;
        float dA = expf(g_Acum[(((size_t)(b * NCHUNK) + c) * NHEADS + h) * CHUNK + (CHUNK - 1)]);
        state = state * dA + g_cs[base + t];
    }
}

// ---------------- SSD stage 3: off-diag + D*x + gate(silu(z)) ---------------
__global__ __launch_bounds__(256) void ssd_offdiag_kernel(const float* __restrict__ Dp)
{
    __shared__ float sp[CHUNK][D_STATE];
    __shared__ float Csh[CHUNK][D_STATE];
    __shared__ float eA[CHUNK];

    const int c = blockIdx.x, h = blockIdx.y, b = blockIdx.z;
    const int t = threadIdx.x;
    const int m0 = b * SEQ + c * CHUNK;
    size_t spbase = (((size_t)(b * NCHUNK) + c) * NHEADS + h) * (HEADDIM * D_STATE);

    #pragma unroll
    for (int i = 0; i < 4; i++) {
        int idx = t + i * 256;
        ((float*)sp)[idx] = g_sp[spbase + idx];
        int s = idx >> 4, n = idx & 15;
        Csh[s][n] = g_xBC[(size_t)(m0 + s) * CONV_DIM + D_INNER + D_STATE + n];
    }
    if (t < CHUNK)
        eA[t] = expf(g_Acum[(((size_t)(b * NCHUNK) + c) * NHEADS + h) * CHUNK + t]);
    __syncthreads();

    const float Dh = Dp[h];
    const int p = t & 63;
    const int lbase = (t >> 6) * 16;

    float spr[D_STATE];
    #pragma unroll
    for (int n = 0; n < D_STATE; n++) spr[n] = sp[p][n];

    for (int i = 0; i < 16; i++) {
        int l = lbase + i;
        int m = m0 + l;
        float d = 0.f;
        #pragma unroll
        for (int n = 0; n < D_STATE; n++) d += Csh[l][n] * spr[n];
        size_t yi = (size_t)m * D_INNER + h * HEADDIM + p;
        float yv = g_y[yi] + eA[l] * d;
        yv += Dh * g_xBC[(size_t)m * CONV_DIM + h * HEADDIM + p];
        float z = g_zxbcdt[(size_t)m * D_IN_PROJ + h * HEADDIM + p];
        yv *= z / (1.f + expf(-z));
        g_y[yi] = yv;
    }
}

// ---------------- RMSNorm over D_INNER + bf16 hi/lo split output ------------
__global__ __launch_bounds__(256) void rmsnorm_split_kernel(const float* __restrict__ norm_w)
{
    const int m = blockIdx.x;
    const int t = threadIdx.x;
    size_t base = (size_t)m * D_INNER;
    float s = 0.f;
    for (int i = t; i < D_INNER; i += 256) {
        float v = g_y[base + i];
        s += v * v;
    }
    __shared__ float red[256];
    red[t] = s; __syncthreads();
    for (int o = 128; o > 0; o >>= 1) {
        if (t < o) red[t] += red[t + o];
        __syncthreads();
    }
    float scale = rsqrtf(red[0] / (float)D_INNER + 1e-5f);
    for (int i = t; i < D_INNER; i += 256) {
        float v = g_y[base + i] * scale * norm_w[i];
        __nv_bfloat16 h = __float2bfloat16_rn(v);
        __nv_bfloat16 l = __float2bfloat16_rn(v - __bfloat162float(h));
        g_yhi[base + i] = *(unsigned short*)&h;
        g_ylo[base + i] = *(unsigned short*)&l;
    }
}

// ---------------- launch ----------------------------------------------------
extern "C" void kernel_launch(void* const* d_in, const int* in_sizes, int n_in,
                              void* d_out, int out_size)
{
    const float* u       = (const float*)d_in[0];
    const float* W_in    = (const float*)d_in[1];
    const float* conv_w  = (const float*)d_in[2];
    const float* conv_b  = (const float*)d_in[3];
    const float* dt_bias = (const float*)d_in[4];
    const float* A_log   = (const float*)d_in[5];
    const float* Dp      = (const float*)d_in[6];
    const float* norm_w  = (const float*)d_in[7];
    const float* W_out   = (const float*)d_in[8];
    float* out = (float*)d_out;

    float* zx;
    unsigned short *uhi, *ulo, *w1hi, *w1lo, *yhi, *ylo, *w2hi, *w2lo;
    cudaGetSymbolAddress((void**)&zx, g_zxbcdt);
    cudaGetSymbolAddress((void**)&uhi, g_uhi);
    cudaGetSymbolAddress((void**)&ulo, g_ulo);
    cudaGetSymbolAddress((void**)&w1hi, g_w1hi);
    cudaGetSymbolAddress((void**)&w1lo, g_w1lo);
    cudaGetSymbolAddress((void**)&yhi, g_yhi);
    cudaGetSymbolAddress((void**)&ylo, g_ylo);
    cudaGetSymbolAddress((void**)&w2hi, g_w2hi);
    cudaGetSymbolAddress((void**)&w2lo, g_w2lo);

    cudaFuncSetAttribute(bf16gemm3, cudaFuncAttributeMaxDynamicSharedMemorySize, GSMEM);

    // 0. split inputs to bf16 hi/lo
    split_kernel<<<(MTOT * D_MODEL) / 1024, 256>>>(u, uhi, ulo, MTOT * D_MODEL);
    split_kernel<<<(D_IN_PROJ * D_MODEL) / 1024, 256>>>(W_in, w1hi, w1lo, D_IN_PROJ * D_MODEL);
    split_kernel<<<(D_MODEL * D_INNER) / 1024, 256>>>(W_out, w2hi, w2lo, D_MODEL * D_INNER);

    // 1. in_proj:  zxbcdt = u @ W_in^T   (8192 x 4160 x 1024)
    bf16gemm3<<<dim3((D_IN_PROJ + BN - 1) / BN, MTOT / BM), 256, GSMEM>>>(
        uhi, ulo, w1hi, w1lo, zx, MTOT, D_IN_PROJ, D_MODEL);

    // 2. depthwise conv + silu on xBC slice
    conv_silu_kernel<<<(MTOT * CONV_DIM + 255) / 256, 256>>>(conv_w, conv_b);

    // 3. dt = softplus(raw + bias)
    dt_kernel<<<(MTOT * NHEADS + 255) / 256, 256>>>(dt_bias);

    // 4. SSD intra-chunk (Y_diag + chunk states)
    ssd_chunk_kernel<<<dim3(NCHUNK, NHEADS, BATCH), 256>>>(A_log);

    // 5. sequential cross-chunk scan
    ssd_scan_kernel<<<BATCH * NHEADS, 1024>>>();

    // 6. off-diagonal contribution + D*x + gating
    ssd_offdiag_kernel<<<dim3(NCHUNK, NHEADS, BATCH), 256>>>(Dp);

    // 7. RMSNorm (+ bf16 split of y for out_proj)
    rmsnorm_split_kernel<<<MTOT, 256>>>(norm_w);

    // 8. out_proj: out = y @ W_out^T   (8192 x 1024 x 2048)
    bf16gemm3<<<dim3(D_MODEL / BN, MTOT / BM), 256, GSMEM>>>(
        yhi, ylo, w2hi, w2lo, out, MTOT, D_MODEL, D_INNER);
}

// round 6
// speedup vs baseline: 2.4809x; 1.0399x over previous
#include <cuda_runtime.h>
#include <cuda_bf16.h>
#include <math.h>
#include <stdint.h>

#define D_MODEL   1024
#define D_STATE   16
#define D_CONV    4
#define HEADDIM   64
#define CHUNK     64
#define D_INNER   2048
#define NHEADS    32
#define CONV_DIM  2080          // D_INNER + 2*D_STATE
#define D_IN_PROJ 4160          // 2*D_INNER + 2*D_STATE + NHEADS
#define BATCH     2
#define SEQ       4096
#define NCHUNK    (SEQ / CHUNK) // 64
#define MTOT      (BATCH * SEQ) // 8192

// ---------------- scratch (device globals; no allocation allowed) -----------
__device__ float g_zxbcdt[(size_t)MTOT * D_IN_PROJ];
__device__ float g_xBC[(size_t)MTOT * CONV_DIM];
__device__ float g_dt[(size_t)MTOT * NHEADS];
__device__ float g_Acum[(size_t)BATCH * NCHUNK * NHEADS * CHUNK];
__device__ float g_cs[(size_t)BATCH * NCHUNK * NHEADS * HEADDIM * D_STATE];
__device__ float g_sp[(size_t)BATCH * NCHUNK * NHEADS * HEADDIM * D_STATE];
__device__ float g_y[(size_t)MTOT * D_INNER];

// bf16 hi/lo split buffers
__device__ unsigned short g_uhi[(size_t)MTOT * D_MODEL];
__device__ unsigned short g_ulo[(size_t)MTOT * D_MODEL];
__device__ unsigned short g_w1hi[(size_t)D_IN_PROJ * D_MODEL];
__device__ unsigned short g_w1lo[(size_t)D_IN_PROJ * D_MODEL];
__device__ unsigned short g_yhi[(size_t)MTOT * D_INNER];
__device__ unsigned short g_ylo[(size_t)MTOT * D_INNER];
__device__ unsigned short g_w2hi[(size_t)D_MODEL * D_INNER];
__device__ unsigned short g_w2lo[(size_t)D_MODEL * D_INNER];

// ============================================================================
// helpers
// ============================================================================
__device__ __forceinline__ uint32_t cvta_s(const void* p) {
    uint32_t a;
    asm("{ .reg .u64 t; cvta.to.shared.u64 t, %1; cvt.u32.u64 %0, t; }" : "=r"(a) : "l"(p));
    return a;
}
__device__ __forceinline__ void cpa16(uint32_t dst, const void* src, int sz) {
    asm volatile("cp.async.cg.shared.global [%0], [%1], 16, %2;"
                 :: "r"(dst), "l"(src), "r"(sz));
}
#define CP_COMMIT() asm volatile("cp.async.commit_group;" ::: "memory")
#define CP_WAIT2()  asm volatile("cp.async.wait_group 2;" ::: "memory")

__device__ __forceinline__ void ldm_x4(uint32_t& r0, uint32_t& r1, uint32_t& r2,
                                       uint32_t& r3, uint32_t addr) {
    asm volatile("ldmatrix.sync.aligned.m8n8.x4.shared.b16 {%0,%1,%2,%3}, [%4];"
                 : "=r"(r0), "=r"(r1), "=r"(r2), "=r"(r3) : "r"(addr));
}
__device__ __forceinline__ void mma_bf16(float* d, const uint32_t* a, const uint32_t* b) {
    asm volatile(
        "mma.sync.aligned.m16n8k16.row.col.f32.bf16.bf16.f32 "
        "{%0,%1,%2,%3},{%4,%5,%6,%7},{%8,%9},{%0,%1,%2,%3};"
        : "+f"(d[0]), "+f"(d[1]), "+f"(d[2]), "+f"(d[3])
        : "r"(a[0]), "r"(a[1]), "r"(a[2]), "r"(a[3]), "r"(b[0]), "r"(b[1]));
}

// ============================================================================
// bf16 3-term split GEMM: C[M,N] = A[M,K] @ B[N,K]^T (fp32 accuracy ~1e-5)
// Terms along K: [Ahi*Bhi | Ahi*Blo | Alo*Bhi]. CTA tile 128x256, BK=64,
// 4-stage cp.async pipeline, 8 warps (2x4), warp tile 64x64 ->
// per k16 step: 4 A-ldmatrix.x4 + 4 B-ldmatrix.x4 feed 32 MMAs.
// ============================================================================
#define BM 128
#define BN 256
#define BKG 64
#define STG 4
#define ATILE (BM * BKG * 2)       // 16384 B
#define BTILE (BN * BKG * 2)       // 32768 B
#define STGB (ATILE + BTILE)       // 49152 B
#define GSMEM (STG * STGB)         // 196608 B

__global__ __launch_bounds__(256, 1) void bf16gemm3(
    const unsigned short* __restrict__ Ahi, const unsigned short* __restrict__ Alo,
    const unsigned short* __restrict__ Bhi, const unsigned short* __restrict__ Blo,
    float* __restrict__ C, int M, int N, int K)
{
    extern __shared__ char smraw[];
    const uint32_t smb = cvta_s(smraw);
    const int tid = threadIdx.x, lane = tid & 31, wid = tid >> 5;
    const int wm = (wid & 1) * 64, wn = (wid >> 1) * 64;
    const int qr = lane >> 2, qc = lane & 3;
    const int brow = blockIdx.y * BM, bcol = blockIdx.x * BN;
    const int KBblk = K >> 6, KBt = 3 * KBblk;

    float acc[4][8][4];
    #pragma unroll
    for (int mi = 0; mi < 4; mi++)
        #pragma unroll
        for (int ni = 0; ni < 8; ni++)
            #pragma unroll
            for (int r = 0; r < 4; r++) acc[mi][ni][r] = 0.f;

    auto issue = [&](int kb) {
        if (kb >= KBt) return;
        const unsigned short *pa, *pb; int kk;
        if (kb < KBblk)          { pa = Ahi; pb = Bhi; kk = kb; }
        else if (kb < 2 * KBblk) { pa = Ahi; pb = Blo; kk = kb - KBblk; }
        else                     { pa = Alo; pb = Bhi; kk = kb - 2 * KBblk; }
        const int st = kb & (STG - 1);
        const uint32_t abase = smb + st * STGB;
        const uint32_t bbase = abase + ATILE;
        #pragma unroll
        for (int p = 0; p < 4; p++) {               // A: 1024 granules
            int g = tid + p * 256;
            int r = g >> 3, cg = g & 7;
            cpa16(abase + r * 128 + ((cg ^ (r & 7)) * 16),
                  pa + (size_t)(brow + r) * K + kk * BKG + cg * 8, 16);
        }
        #pragma unroll
        for (int p = 0; p < 8; p++) {               // B: 2048 granules
            int g = tid + p * 256;
            int r = g >> 3, cg = g & 7;
            int bn = bcol + r;
            cpa16(bbase + r * 128 + ((cg ^ (r & 7)) * 16),
                  pb + (size_t)(bn < N ? bn : 0) * K + kk * BKG + cg * 8,
                  bn < N ? 16 : 0);
        }
    };

    issue(0); CP_COMMIT();
    issue(1); CP_COMMIT();
    issue(2); CP_COMMIT();

    for (int kb = 0; kb < KBt; kb++) {
        CP_WAIT2();
        __syncthreads();
        issue(kb + 3); CP_COMMIT();

        const int st = kb & (STG - 1);
        const uint32_t abase = smb + st * STGB;
        const uint32_t bbase = abase + ATILE;
        #pragma unroll
        for (int ks = 0; ks < 4; ks++) {
            uint32_t af[4][4], bfr[8][2];
            #pragma unroll
            for (int mi = 0; mi < 4; mi++) {
                int r = wm + mi * 16 + (lane & 15);
                int g = (ks * 2 + (lane >> 4)) ^ (r & 7);
                ldm_x4(af[mi][0], af[mi][1], af[mi][2], af[mi][3],
                       abase + r * 128 + g * 16);
            }
            #pragma unroll
            for (int pi = 0; pi < 4; pi++) {
                int r = wn + pi * 16 + (lane & 7) + (((lane >> 4) & 1) << 3);
                int g = (ks * 2 + ((lane >> 3) & 1)) ^ (r & 7);
                ldm_x4(bfr[pi * 2][0], bfr[pi * 2][1],
                       bfr[pi * 2 + 1][0], bfr[pi * 2 + 1][1],
                       bbase + r * 128 + g * 16);
            }
            #pragma unroll
            for (int mi = 0; mi < 4; mi++)
                #pragma unroll
                for (int ni = 0; ni < 8; ni++)
                    mma_bf16(acc[mi][ni], af[mi], bfr[ni]);
        }
    }

    // epilogue
    #pragma unroll
    for (int mi = 0; mi < 4; mi++) {
        int row0 = brow + wm + mi * 16 + qr;
        #pragma unroll
        for (int ni = 0; ni < 8; ni++) {
            int col = bcol + wn + ni * 8 + qc * 2;
            if (col < N) {
                *(float2*)(C + (size_t)row0 * N + col) =
                    make_float2(acc[mi][ni][0], acc[mi][ni][1]);
                *(float2*)(C + (size_t)(row0 + 8) * N + col) =
                    make_float2(acc[mi][ni][2], acc[mi][ni][3]);
            }
        }
    }
}

// ---------------- fp32 -> bf16 hi/lo split ----------------------------------
__global__ void split_kernel(const float* __restrict__ s,
                             unsigned short* __restrict__ hi,
                             unsigned short* __restrict__ lo, int n)
{
    int i = (blockIdx.x * 256 + threadIdx.x) * 4;
    if (i >= n) return;
    float4 v = *(const float4*)(s + i);
    __nv_bfloat16 h0 = __float2bfloat16_rn(v.x);
    __nv_bfloat16 h1 = __float2bfloat16_rn(v.y);
    __nv_bfloat16 h2 = __float2bfloat16_rn(v.z);
    __nv_bfloat16 h3 = __float2bfloat16_rn(v.w);
    __nv_bfloat16 l0 = __float2bfloat16_rn(v.x - __bfloat162float(h0));
    __nv_bfloat16 l1 = __float2bfloat16_rn(v.y - __bfloat162float(h1));
    __nv_bfloat16 l2 = __float2bfloat16_rn(v.z - __bfloat162float(h2));
    __nv_bfloat16 l3 = __float2bfloat16_rn(v.w - __bfloat162float(h3));
    *(ushort4*)(hi + i) = make_ushort4(*(unsigned short*)&h0, *(unsigned short*)&h1,
                                       *(unsigned short*)&h2, *(unsigned short*)&h3);
    *(ushort4*)(lo + i) = make_ushort4(*(unsigned short*)&l0, *(unsigned short*)&l1,
                                       *(unsigned short*)&l2, *(unsigned short*)&l3);
}

// ---------------- depthwise causal conv(4) + bias + SiLU --------------------
__global__ void conv_silu_kernel(const float* __restrict__ conv_w,
                                 const float* __restrict__ conv_b)
{
    int idx = blockIdx.x * blockDim.x + threadIdx.x;
    if (idx >= MTOT * CONV_DIM) return;
    int c = idx % CONV_DIM;
    int m = idx / CONV_DIM;
    int l = m & (SEQ - 1);

    float acc = conv_b[c];
    #pragma unroll
    for (int j = 0; j < D_CONV; j++) {
        int lj = l - (D_CONV - 1) + j;
        if (lj >= 0)
            acc += conv_w[c * D_CONV + j] *
                   g_zxbcdt[(size_t)(m - (D_CONV - 1) + j) * D_IN_PROJ + D_INNER + c];
    }
    g_xBC[idx] = acc / (1.f + expf(-acc));
}

// ---------------- dt = softplus(raw + bias) ---------------------------------
__global__ void dt_kernel(const float* __restrict__ dt_bias)
{
    int idx = blockIdx.x * blockDim.x + threadIdx.x;
    if (idx >= MTOT * NHEADS) return;
    int h = idx & (NHEADS - 1);
    int m = idx >> 5;
    float x = g_zxbcdt[(size_t)m * D_IN_PROJ + (D_IN_PROJ - NHEADS) + h] + dt_bias[h];
    g_dt[idx] = (x > 20.f) ? x : log1pf(expf(x));
}

// ---------------- SSD stage 1: per-chunk diag output + chunk states ---------
__global__ __launch_bounds__(256) void ssd_chunk_kernel(const float* __restrict__ A_log)
{
    __shared__ float xs[CHUNK][HEADDIM];
    __shared__ float Gs[CHUNK][CHUNK];
    __shared__ float Bsh[CHUNK][D_STATE];
    __shared__ float Csh[CHUNK][D_STATE];
    __shared__ float Acum[CHUNK];
    __shared__ float dts[CHUNK];
    __shared__ float decay[CHUNK];

    const int c = blockIdx.x, h = blockIdx.y, b = blockIdx.z;
    const int t = threadIdx.x;
    const int m0 = b * SEQ + c * CHUNK;

    if (t < CHUNK) dts[t] = g_dt[(size_t)(m0 + t) * NHEADS + h];
    #pragma unroll
    for (int i = 0; i < 4; i++) {
        int idx = t + i * 256;
        int s = idx >> 4, n = idx & 15;
        Bsh[s][n] = g_xBC[(size_t)(m0 + s) * CONV_DIM + D_INNER + n];
        Csh[s][n] = g_xBC[(size_t)(m0 + s) * CONV_DIM + D_INNER + D_STATE + n];
    }
    __syncthreads();
    #pragma unroll
    for (int i = 0; i < 16; i++) {
        int idx = t + i * 256;
        int s = idx >> 6, p = idx & 63;
        xs[s][p] = g_xBC[(size_t)(m0 + s) * CONV_DIM + h * HEADDIM + p] * dts[s];
    }
    __syncthreads();

    if (t == 0) {
        float Ah = -expf(A_log[h]);
        float run = 0.f;
        for (int s = 0; s < CHUNK; s++) { run += Ah * dts[s]; Acum[s] = run; }
    }
    __syncthreads();
    float Alast = Acum[CHUNK - 1];
    if (t < CHUNK) {
        decay[t] = expf(Alast - Acum[t]);
        g_Acum[(((size_t)(b * NCHUNK) + c) * NHEADS + h) * CHUNK + t] = Acum[t];
    }
    __syncthreads();

    #pragma unroll
    for (int i = 0; i < 16; i++) {
        int idx = t + i * 256;
        int l = idx >> 6, s = idx & 63;
        float g = 0.f;
        if (s <= l) {
            float d = 0.f;
            #pragma unroll
            for (int n = 0; n < D_STATE; n++) d += Csh[l][n] * Bsh[s][n];
            g = d * expf(Acum[l] - Acum[s]);
        }
        Gs[l][s] = g;
    }
    __syncthreads();

    // Y_diag = G @ x, s-unrolled by 4, all-float4 shared reads
    {
        const int p0 = (t & 15) * 4;
        const int l0 = (t >> 4) * 4;
        float acc[4][4];
        #pragma unroll
        for (int i = 0; i < 4; i++)
            #pragma unroll
            for (int j = 0; j < 4; j++) acc[i][j] = 0.f;
        for (int s0 = 0; s0 < CHUNK; s0 += 4) {
            float4 xq[4];
            #pragma unroll
            for (int j = 0; j < 4; j++) xq[j] = *(const float4*)&xs[s0 + j][p0];
            #pragma unroll
            for (int i = 0; i < 4; i++) {
                float4 gq = *(const float4*)&Gs[l0 + i][s0];
                acc[i][0] += gq.x * xq[0].x + gq.y * xq[1].x + gq.z * xq[2].x + gq.w * xq[3].x;
                acc[i][1] += gq.x * xq[0].y + gq.y * xq[1].y + gq.z * xq[2].y + gq.w * xq[3].y;
                acc[i][2] += gq.x * xq[0].z + gq.y * xq[1].z + gq.z * xq[2].z + gq.w * xq[3].z;
                acc[i][3] += gq.x * xq[0].w + gq.y * xq[1].w + gq.z * xq[2].w + gq.w * xq[3].w;
            }
        }
        #pragma unroll
        for (int i = 0; i < 4; i++)
            *(float4*)&g_y[(size_t)(m0 + l0 + i) * D_INNER + h * HEADDIM + p0] =
                make_float4(acc[i][0], acc[i][1], acc[i][2], acc[i][3]);
    }

    {
        const int p  = t & 63;
        const int nb = (t >> 6) * 4;
        float acc[4] = {0.f, 0.f, 0.f, 0.f};
        for (int s = 0; s < CHUNK; s++) {
            float xv = xs[s][p] * decay[s];
            #pragma unroll
            for (int j = 0; j < 4; j++) acc[j] += Bsh[s][nb + j] * xv;
        }
        size_t base = ((((size_t)(b * NCHUNK) + c) * NHEADS + h) * HEADDIM + p) * D_STATE + nb;
        #pragma unroll
        for (int j = 0; j < 4; j++) g_cs[base + j] = acc[j];
    }
}

// ---------------- SSD stage 2: sequential cross-chunk state scan ------------
__global__ __launch_bounds__(1024) void ssd_scan_kernel()
{
    const int bh = blockIdx.x;
    const int b = bh / NHEADS, h = bh % NHEADS;
    const int t = threadIdx.x;
    float state = 0.f;
    for (int c = 0; c < NCHUNK; c++) {
        size_t base = (((size_t)(b * NCHUNK) + c) * NHEADS + h) * (HEADDIM * D_STATE);
        g_sp[base + t] = state;
        float dA = expf(g_Acum[(((size_t)(b * NCHUNK) + c) * NHEADS + h) * CHUNK + (CHUNK - 1)]);
        state = state * dA + g_cs[base + t];
    }
}

// ---------------- SSD stage 3: off-diag + D*x + gate(silu(z)) ---------------
__global__ __launch_bounds__(256) void ssd_offdiag_kernel(const float* __restrict__ Dp)
{
    __shared__ float sp[CHUNK][D_STATE];
    __shared__ float Csh[CHUNK][D_STATE];
    __shared__ float eA[CHUNK];

    const int c = blockIdx.x, h = blockIdx.y, b = blockIdx.z;
    const int t = threadIdx.x;
    const int m0 = b * SEQ + c * CHUNK;
    size_t spbase = (((size_t)(b * NCHUNK) + c) * NHEADS + h) * (HEADDIM * D_STATE);

    #pragma unroll
    for (int i = 0; i < 4; i++) {
        int idx = t + i * 256;
        ((float*)sp)[idx] = g_sp[spbase + idx];
        int s = idx >> 4, n = idx & 15;
        Csh[s][n] = g_xBC[(size_t)(m0 + s) * CONV_DIM + D_INNER + D_STATE + n];
    }
    if (t < CHUNK)
        eA[t] = expf(g_Acum[(((size_t)(b * NCHUNK) + c) * NHEADS + h) * CHUNK + t]);
    __syncthreads();

    const float Dh = Dp[h];
    const int p = t & 63;
    const int lbase = (t >> 6) * 16;

    float spr[D_STATE];
    #pragma unroll
    for (int n = 0; n < D_STATE; n++) spr[n] = sp[p][n];

    for (int i = 0; i < 16; i++) {
        int l = lbase + i;
        int m = m0 + l;
        float d = 0.f;
        #pragma unroll
        for (int n = 0; n < D_STATE; n++) d += Csh[l][n] * spr[n];
        size_t yi = (size_t)m * D_INNER + h * HEADDIM + p;
        float yv = g_y[yi] + eA[l] * d;
        yv += Dh * g_xBC[(size_t)m * CONV_DIM + h * HEADDIM + p];
        float z = g_zxbcdt[(size_t)m * D_IN_PROJ + h * HEADDIM + p];
        yv *= z / (1.f + expf(-z));
        g_y[yi] = yv;
    }
}

// ---------------- RMSNorm over D_INNER + bf16 hi/lo split output ------------
__global__ __launch_bounds__(256) void rmsnorm_split_kernel(const float* __restrict__ norm_w)
{
    const int m = blockIdx.x;
    const int t = threadIdx.x;
    size_t base = (size_t)m * D_INNER;
    float s = 0.f;
    for (int i = t; i < D_INNER; i += 256) {
        float v = g_y[base + i];
        s += v * v;
    }
    __shared__ float red[256];
    red[t] = s; __syncthreads();
    for (int o = 128; o > 0; o >>= 1) {
        if (t < o) red[t] += red[t + o];
        __syncthreads();
    }
    float scale = rsqrtf(red[0] / (float)D_INNER + 1e-5f);
    for (int i = t; i < D_INNER; i += 256) {
        float v = g_y[base + i] * scale * norm_w[i];
        __nv_bfloat16 h = __float2bfloat16_rn(v);
        __nv_bfloat16 l = __float2bfloat16_rn(v - __bfloat162float(h));
        g_yhi[base + i] = *(unsigned short*)&h;
        g_ylo[base + i] = *(unsigned short*)&l;
    }
}

// ---------------- launch ----------------------------------------------------
extern "C" void kernel_launch(void* const* d_in, const int* in_sizes, int n_in,
                              void* d_out, int out_size)
{
    const float* u       = (const float*)d_in[0];
    const float* W_in    = (const float*)d_in[1];
    const float* conv_w  = (const float*)d_in[2];
    const float* conv_b  = (const float*)d_in[3];
    const float* dt_bias = (const float*)d_in[4];
    const float* A_log   = (const float*)d_in[5];
    const float* Dp      = (const float*)d_in[6];
    const float* norm_w  = (const float*)d_in[7];
    const float* W_out   = (const float*)d_in[8];
    float* out = (float*)d_out;

    float* zx;
    unsigned short *uhi, *ulo, *w1hi, *w1lo, *yhi, *ylo, *w2hi, *w2lo;
    cudaGetSymbolAddress((void**)&zx, g_zxbcdt);
    cudaGetSymbolAddress((void**)&uhi, g_uhi);
    cudaGetSymbolAddress((void**)&ulo, g_ulo);
    cudaGetSymbolAddress((void**)&w1hi, g_w1hi);
    cudaGetSymbolAddress((void**)&w1lo, g_w1lo);
    cudaGetSymbolAddress((void**)&yhi, g_yhi);
    cudaGetSymbolAddress((void**)&ylo, g_ylo);
    cudaGetSymbolAddress((void**)&w2hi, g_w2hi);
    cudaGetSymbolAddress((void**)&w2lo, g_w2lo);

    cudaFuncSetAttribute(bf16gemm3, cudaFuncAttributeMaxDynamicSharedMemorySize, GSMEM);

    // 0. split inputs to bf16 hi/lo
    split_kernel<<<(MTOT * D_MODEL) / 1024, 256>>>(u, uhi, ulo, MTOT * D_MODEL);
    split_kernel<<<(D_IN_PROJ * D_MODEL) / 1024, 256>>>(W_in, w1hi, w1lo, D_IN_PROJ * D_MODEL);
    split_kernel<<<(D_MODEL * D_INNER) / 1024, 256>>>(W_out, w2hi, w2lo, D_MODEL * D_INNER);

    // 1. in_proj:  zxbcdt = u @ W_in^T   (8192 x 4160 x 1024)
    bf16gemm3<<<dim3((D_IN_PROJ + BN - 1) / BN, MTOT / BM), 256, GSMEM>>>(
        uhi, ulo, w1hi, w1lo, zx, MTOT, D_IN_PROJ, D_MODEL);

    // 2. depthwise conv + silu on xBC slice
    conv_silu_kernel<<<(MTOT * CONV_DIM + 255) / 256, 256>>>(conv_w, conv_b);

    // 3. dt = softplus(raw + bias)
    dt_kernel<<<(MTOT * NHEADS + 255) / 256, 256>>>(dt_bias);

    // 4. SSD intra-chunk (Y_diag + chunk states)
    ssd_chunk_kernel<<<dim3(NCHUNK, NHEADS, BATCH), 256>>>(A_log);

    // 5. sequential cross-chunk scan
    ssd_scan_kernel<<<BATCH * NHEADS, 1024>>>();

    // 6. off-diagonal contribution + D*x + gating
    ssd_offdiag_kernel<<<dim3(NCHUNK, NHEADS, BATCH), 256>>>(Dp);

    // 7. RMSNorm (+ bf16 split of y for out_proj)
    rmsnorm_split_kernel<<<MTOT, 256>>>(norm_w);

    // 8. out_proj: out = y @ W_out^T   (8192 x 1024 x 2048)
    bf16gemm3<<<dim3(D_MODEL / BN, MTOT / BM), 256, GSMEM>>>(
        yhi, ylo, w2hi, w2lo, out, MTOT, D_MODEL, D_INNER);
}

// round 8
// speedup vs baseline: 2.6662x; 1.0747x over previous
#include <cuda_runtime.h>
#include <cuda_bf16.h>
#include <math.h>
#include <stdint.h>

#define D_MODEL   1024
#define D_STATE   16
#define D_CONV    4
#define HEADDIM   64
#define CHUNK     64
#define D_INNER   2048
#define NHEADS    32
#define CONV_DIM  2080          // D_INNER + 2*D_STATE
#define D_IN_PROJ 4160          // 2*D_INNER + 2*D_STATE + NHEADS
#define BATCH     2
#define SEQ       4096
#define NCHUNK    (SEQ / CHUNK) // 64
#define MTOT      (BATCH * SEQ) // 8192

// ---------------- scratch (device globals; no allocation allowed) -----------
__device__ float g_zxbcdt[(size_t)MTOT * D_IN_PROJ];
__device__ float g_xBC[(size_t)MTOT * CONV_DIM];
__device__ float g_dt[(size_t)MTOT * NHEADS];
__device__ float g_Acum[(size_t)BATCH * NCHUNK * NHEADS * CHUNK];
__device__ float g_cs[(size_t)BATCH * NCHUNK * NHEADS * HEADDIM * D_STATE];
__device__ float g_sp[(size_t)BATCH * NCHUNK * NHEADS * HEADDIM * D_STATE];
__device__ float g_y[(size_t)MTOT * D_INNER];

// bf16 hi/lo split buffers
__device__ unsigned short g_uhi[(size_t)MTOT * D_MODEL];
__device__ unsigned short g_ulo[(size_t)MTOT * D_MODEL];
__device__ unsigned short g_w1hi[(size_t)D_IN_PROJ * D_MODEL];
__device__ unsigned short g_w1lo[(size_t)D_IN_PROJ * D_MODEL];
__device__ unsigned short g_yhi[(size_t)MTOT * D_INNER];
__device__ unsigned short g_ylo[(size_t)MTOT * D_INNER];
__device__ unsigned short g_w2hi[(size_t)D_MODEL * D_INNER];
__device__ unsigned short g_w2lo[(size_t)D_MODEL * D_INNER];

// ============================================================================
// helpers
// ============================================================================
__device__ __forceinline__ uint32_t cvta_s(const void* p) {
    uint32_t a;
    asm("{ .reg .u64 t; cvta.to.shared.u64 t, %1; cvt.u32.u64 %0, t; }" : "=r"(a) : "l"(p));
    return a;
}
__device__ __forceinline__ void cpa16(uint32_t dst, const void* src, int sz) {
    asm volatile("cp.async.cg.shared.global [%0], [%1], 16, %2;"
                 :: "r"(dst), "l"(src), "r"(sz));
}
#define CP_COMMIT() asm volatile("cp.async.commit_group;" ::: "memory")
#define CP_WAIT1()  asm volatile("cp.async.wait_group 1;" ::: "memory")

__device__ __forceinline__ void ldm_x4(uint32_t& r0, uint32_t& r1, uint32_t& r2,
                                       uint32_t& r3, uint32_t addr) {
    asm volatile("ldmatrix.sync.aligned.m8n8.x4.shared.b16 {%0,%1,%2,%3}, [%4];"
                 : "=r"(r0), "=r"(r1), "=r"(r2), "=r"(r3) : "r"(addr));
}
__device__ __forceinline__ void mma_bf16(float* d, const uint32_t* a, const uint32_t* b) {
    asm volatile(
        "mma.sync.aligned.m16n8k16.row.col.f32.bf16.bf16.f32 "
        "{%0,%1,%2,%3},{%4,%5,%6,%7},{%8,%9},{%0,%1,%2,%3};"
        : "+f"(d[0]), "+f"(d[1]), "+f"(d[2]), "+f"(d[3])
        : "r"(a[0]), "r"(a[1]), "r"(a[2]), "r"(a[3]), "r"(b[0]), "r"(b[1]));
}

// ============================================================================
// bf16 3-term split GEMM: C[M,N] = A[M,K] @ B[N,K]^T (fp32 accuracy ~1e-5)
// Terms along K: [Ahi*Bhi | Ahi*Blo | Alo*Bhi]. CTA tile 128x128, BK=64,
// 128 threads (4 warps 2x2), warp tile 64x64, 3-stage cp.async pipeline.
// 96KB smem/CTA -> 2 CTAs resident per SM (independent sync domains).
// ============================================================================
#define BM 128
#define BN 128
#define BKG 64
#define STG 3
#define NTHR 128
#define ATILE (BM * BKG * 2)       // 16384 B
#define BTILE (BN * BKG * 2)       // 16384 B
#define STGB (ATILE + BTILE)       // 32768 B
#define GSMEM (STG * STGB)         // 98304 B

__global__ __launch_bounds__(NTHR, 2) void bf16gemm3(
    const unsigned short* __restrict__ Ahi, const unsigned short* __restrict__ Alo,
    const unsigned short* __restrict__ Bhi, const unsigned short* __restrict__ Blo,
    float* __restrict__ C, int M, int N, int K)
{
    extern __shared__ char smraw[];
    const uint32_t smb = cvta_s(smraw);
    const int tid = threadIdx.x, lane = tid & 31, wid = tid >> 5;
    const int wm = (wid & 1) * 64, wn = (wid >> 1) * 64;
    const int qr = lane >> 2, qc = lane & 3;
    const int brow = blockIdx.y * BM, bcol = blockIdx.x * BN;
    const int KBblk = K >> 6, KBt = 3 * KBblk;

    float acc[4][8][4];
    #pragma unroll
    for (int mi = 0; mi < 4; mi++)
        #pragma unroll
        for (int ni = 0; ni < 8; ni++)
            #pragma unroll
            for (int r = 0; r < 4; r++) acc[mi][ni][r] = 0.f;

    auto issue = [&](int kb) {
        if (kb >= KBt) return;
        const unsigned short *pa, *pb; int kk;
        if (kb < KBblk)          { pa = Ahi; pb = Bhi; kk = kb; }
        else if (kb < 2 * KBblk) { pa = Ahi; pb = Blo; kk = kb - KBblk; }
        else                     { pa = Alo; pb = Bhi; kk = kb - 2 * KBblk; }
        const int st = kb % STG;
        const uint32_t abase = smb + st * STGB;
        const uint32_t bbase = abase + ATILE;
        #pragma unroll
        for (int p = 0; p < 8; p++) {               // A: 1024 16B granules
            int g = tid + p * NTHR;
            int r = g >> 3, cg = g & 7;
            cpa16(abase + r * 128 + ((cg ^ (r & 7)) * 16),
                  pa + (size_t)(brow + r) * K + kk * BKG + cg * 8, 16);
        }
        #pragma unroll
        for (int p = 0; p < 8; p++) {               // B: 1024 16B granules
            int g = tid + p * NTHR;
            int r = g >> 3, cg = g & 7;
            int bn = bcol + r;
            cpa16(bbase + r * 128 + ((cg ^ (r & 7)) * 16),
                  pb + (size_t)(bn < N ? bn : 0) * K + kk * BKG + cg * 8,
                  bn < N ? 16 : 0);
        }
    };

    issue(0); CP_COMMIT();
    issue(1); CP_COMMIT();

    for (int kb = 0; kb < KBt; kb++) {
        CP_WAIT1();
        __syncthreads();
        issue(kb + 2); CP_COMMIT();

        const int st = kb % STG;
        const uint32_t abase = smb + st * STGB;
        const uint32_t bbase = abase + ATILE;
        #pragma unroll
        for (int ks = 0; ks < 4; ks++) {
            uint32_t af[4][4], bfr[8][2];
            #pragma unroll
            for (int mi = 0; mi < 4; mi++) {
                int r = wm + mi * 16 + (lane & 15);
                int g = (ks * 2 + (lane >> 4)) ^ (r & 7);
                ldm_x4(af[mi][0], af[mi][1], af[mi][2], af[mi][3],
                       abase + r * 128 + g * 16);
            }
            #pragma unroll
            for (int pi = 0; pi < 4; pi++) {
                int r = wn + pi * 16 + (lane & 7) + (((lane >> 4) & 1) << 3);
                int g = (ks * 2 + ((lane >> 3) & 1)) ^ (r & 7);
                ldm_x4(bfr[pi * 2][0], bfr[pi * 2][1],
                       bfr[pi * 2 + 1][0], bfr[pi * 2 + 1][1],
                       bbase + r * 128 + g * 16);
            }
            #pragma unroll
            for (int mi = 0; mi < 4; mi++)
                #pragma unroll
                for (int ni = 0; ni < 8; ni++)
                    mma_bf16(acc[mi][ni], af[mi], bfr[ni]);
        }
    }

    // epilogue
    #pragma unroll
    for (int mi = 0; mi < 4; mi++) {
        int row0 = brow + wm + mi * 16 + qr;
        #pragma unroll
        for (int ni = 0; ni < 8; ni++) {
            int col = bcol + wn + ni * 8 + qc * 2;
            if (col < N) {
                *(float2*)(C + (size_t)row0 * N + col) =
                    make_float2(acc[mi][ni][0], acc[mi][ni][1]);
                *(float2*)(C + (size_t)(row0 + 8) * N + col) =
                    make_float2(acc[mi][ni][2], acc[mi][ni][3]);
            }
        }
    }
}

// ---------------- fp32 -> bf16 hi/lo split ----------------------------------
__global__ void split_kernel(const float* __restrict__ s,
                             unsigned short* __restrict__ hi,
                             unsigned short* __restrict__ lo, int n)
{
    int i = (blockIdx.x * 256 + threadIdx.x) * 4;
    if (i >= n) return;
    float4 v = *(const float4*)(s + i);
    __nv_bfloat16 h0 = __float2bfloat16_rn(v.x);
    __nv_bfloat16 h1 = __float2bfloat16_rn(v.y);
    __nv_bfloat16 h2 = __float2bfloat16_rn(v.z);
    __nv_bfloat16 h3 = __float2bfloat16_rn(v.w);
    __nv_bfloat16 l0 = __float2bfloat16_rn(v.x - __bfloat162float(h0));
    __nv_bfloat16 l1 = __float2bfloat16_rn(v.y - __bfloat162float(h1));
    __nv_bfloat16 l2 = __float2bfloat16_rn(v.z - __bfloat162float(h2));
    __nv_bfloat16 l3 = __float2bfloat16_rn(v.w - __bfloat162float(h3));
    *(ushort4*)(hi + i) = make_ushort4(*(unsigned short*)&h0, *(unsigned short*)&h1,
                                       *(unsigned short*)&h2, *(unsigned short*)&h3);
    *(ushort4*)(lo + i) = make_ushort4(*(unsigned short*)&l0, *(unsigned short*)&l1,
                                       *(unsigned short*)&l2, *(unsigned short*)&l3);
}

// ---------------- depthwise causal conv(4) + bias + SiLU --------------------
__global__ void conv_silu_kernel(const float* __restrict__ conv_w,
                                 const float* __restrict__ conv_b)
{
    int idx = blockIdx.x * blockDim.x + threadIdx.x;
    if (idx >= MTOT * CONV_DIM) return;
    int c = idx % CONV_DIM;
    int m = idx / CONV_DIM;
    int l = m & (SEQ - 1);

    float acc = conv_b[c];
    #pragma unroll
    for (int j = 0; j < D_CONV; j++) {
        int lj = l - (D_CONV - 1) + j;
        if (lj >= 0)
            acc += conv_w[c * D_CONV + j] *
                   g_zxbcdt[(size_t)(m - (D_CONV - 1) + j) * D_IN_PROJ + D_INNER + c];
    }
    g_xBC[idx] = acc / (1.f + expf(-acc));
}

// ---------------- dt = softplus(raw + bias) ---------------------------------
__global__ void dt_kernel(const float* __restrict__ dt_bias)
{
    int idx = blockIdx.x * blockDim.x + threadIdx.x;
    if (idx >= MTOT * NHEADS) return;
    int h = idx & (NHEADS - 1);
    int m = idx >> 5;
    float x = g_zxbcdt[(size_t)m * D_IN_PROJ + (D_IN_PROJ - NHEADS) + h] + dt_bias[h];
    g_dt[idx] = (x > 20.f) ? x : log1pf(expf(x));
}

// ---------------- SSD stage 1: per-chunk diag output + chunk states ---------
__global__ __launch_bounds__(256) void ssd_chunk_kernel(const float* __restrict__ A_log)
{
    __shared__ float xs[CHUNK][HEADDIM];
    __shared__ float Gs[CHUNK][CHUNK];
    __shared__ float Bsh[CHUNK][D_STATE];
    __shared__ float Csh[CHUNK][D_STATE];
    __shared__ float Acum[CHUNK];
    __shared__ float dts[CHUNK];
    __shared__ float decay[CHUNK];

    const int c = blockIdx.x, h = blockIdx.y, b = blockIdx.z;
    const int t = threadIdx.x;
    const int m0 = b * SEQ + c * CHUNK;

    if (t < CHUNK) dts[t] = g_dt[(size_t)(m0 + t) * NHEADS + h];
    #pragma unroll
    for (int i = 0; i < 4; i++) {
        int idx = t + i * 256;
        int s = idx >> 4, n = idx & 15;
        Bsh[s][n] = g_xBC[(size_t)(m0 + s) * CONV_DIM + D_INNER + n];
        Csh[s][n] = g_xBC[(size_t)(m0 + s) * CONV_DIM + D_INNER + D_STATE + n];
    }
    __syncthreads();
    #pragma unroll
    for (int i = 0; i < 16; i++) {
        int idx = t + i * 256;
        int s = idx >> 6, p = idx & 63;
        xs[s][p] = g_xBC[(size_t)(m0 + s) * CONV_DIM + h * HEADDIM + p] * dts[s];
    }
    __syncthreads();

    if (t == 0) {
        float Ah = -expf(A_log[h]);
        float run = 0.f;
        for (int s = 0; s < CHUNK; s++) { run += Ah * dts[s]; Acum[s] = run; }
    }
    __syncthreads();
    float Alast = Acum[CHUNK - 1];
    if (t < CHUNK) {
        decay[t] = expf(Alast - Acum[t]);
        g_Acum[(((size_t)(b * NCHUNK) + c) * NHEADS + h) * CHUNK + t] = Acum[t];
    }
    __syncthreads();

    #pragma unroll
    for (int i = 0; i < 16; i++) {
        int idx = t + i * 256;
        int l = idx >> 6, s = idx & 63;
        float g = 0.f;
        if (s <= l) {
            float d = 0.f;
            #pragma unroll
            for (int n = 0; n < D_STATE; n++) d += Csh[l][n] * Bsh[s][n];
            g = d * expf(Acum[l] - Acum[s]);
        }
        Gs[l][s] = g;
    }
    __syncthreads();

    // Y_diag = G @ x, s-unrolled by 4, all-float4 shared reads
    {
        const int p0 = (t & 15) * 4;
        const int l0 = (t >> 4) * 4;
        float acc[4][4];
        #pragma unroll
        for (int i = 0; i < 4; i++)
            #pragma unroll
            for (int j = 0; j < 4; j++) acc[i][j] = 0.f;
        for (int s0 = 0; s0 < CHUNK; s0 += 4) {
            float4 xq[4];
            #pragma unroll
            for (int j = 0; j < 4; j++) xq[j] = *(const float4*)&xs[s0 + j][p0];
            #pragma unroll
            for (int i = 0; i < 4; i++) {
                float4 gq = *(const float4*)&Gs[l0 + i][s0];
                acc[i][0] += gq.x * xq[0].x + gq.y * xq[1].x + gq.z * xq[2].x + gq.w * xq[3].x;
                acc[i][1] += gq.x * xq[0].y + gq.y * xq[1].y + gq.z * xq[2].y + gq.w * xq[3].y;
                acc[i][2] += gq.x * xq[0].z + gq.y * xq[1].z + gq.z * xq[2].z + gq.w * xq[3].z;
                acc[i][3] += gq.x * xq[0].w + gq.y * xq[1].w + gq.z * xq[2].w + gq.w * xq[3].w;
            }
        }
        #pragma unroll
        for (int i = 0; i < 4; i++)
            *(float4*)&g_y[(size_t)(m0 + l0 + i) * D_INNER + h * HEADDIM + p0] =
                make_float4(acc[i][0], acc[i][1], acc[i][2], acc[i][3]);
    }

    {
        const int p  = t & 63;
        const int nb = (t >> 6) * 4;
        float acc[4] = {0.f, 0.f, 0.f, 0.f};
        for (int s = 0; s < CHUNK; s++) {
            float xv = xs[s][p] * decay[s];
            #pragma unroll
            for (int j = 0; j < 4; j++) acc[j] += Bsh[s][nb + j] * xv;
        }
        size_t base = ((((size_t)(b * NCHUNK) + c) * NHEADS + h) * HEADDIM + p) * D_STATE + nb;
        #pragma unroll
        for (int j = 0; j < 4; j++) g_cs[base + j] = acc[j];
    }
}

// ---------------- SSD stage 2: sequential cross-chunk state scan ------------
__global__ __launch_bounds__(1024) void ssd_scan_kernel()
{
    const int bh = blockIdx.x;
    const int b = bh / NHEADS, h = bh % NHEADS;
    const int t = threadIdx.x;
    float state = 0.f;
    for (int c = 0; c < NCHUNK; c++) {
        size_t base = (((size_t)(b * NCHUNK) + c) * NHEADS + h) * (HEADDIM * D_STATE);
        g_sp[base + t] = state;
        float dA = expf(g_Acum[(((size_t)(b * NCHUNK) + c) * NHEADS + h) * CHUNK + (CHUNK - 1)]);
        state = state * dA + g_cs[base + t];
    }
}

// ---------------- SSD stage 3: off-diag + D*x + gate(silu(z)) ---------------
__global__ __launch_bounds__(256) void ssd_offdiag_kernel(const float* __restrict__ Dp)
{
    __shared__ float sp[CHUNK][D_STATE];
    __shared__ float Csh[CHUNK][D_STATE];
    __shared__ float eA[CHUNK];

    const int c = blockIdx.x, h = blockIdx.y, b = blockIdx.z;
    const int t = threadIdx.x;
    const int m0 = b * SEQ + c * CHUNK;
    size_t spbase = (((size_t)(b * NCHUNK) + c) * NHEADS + h) * (HEADDIM * D_STATE);

    #pragma unroll
    for (int i = 0; i < 4; i++) {
        int idx = t + i * 256;
        ((float*)sp)[idx] = g_sp[spbase + idx];
        int s = idx >> 4, n = idx & 15;
        Csh[s][n] = g_xBC[(size_t)(m0 + s) * CONV_DIM + D_INNER + D_STATE + n];
    }
    if (t < CHUNK)
        eA[t] = expf(g_Acum[(((size_t)(b * NCHUNK) + c) * NHEADS + h) * CHUNK + t]);
    __syncthreads();

    const float Dh = Dp[h];
    const int p = t & 63;
    const int lbase = (t >> 6) * 16;

    float spr[D_STATE];
    #pragma unroll
    for (int n = 0; n < D_STATE; n++) spr[n] = sp[p][n];

    for (int i = 0; i < 16; i++) {
        int l = lbase + i;
        int m = m0 + l;
        float d = 0.f;
        #pragma unroll
        for (int n = 0; n < D_STATE; n++) d += Csh[l][n] * spr[n];
        size_t yi = (size_t)m * D_INNER + h * HEADDIM + p;
        float yv = g_y[yi] + eA[l] * d;
        yv += Dh * g_xBC[(size_t)m * CONV_DIM + h * HEADDIM + p];
        float z = g_zxbcdt[(size_t)m * D_IN_PROJ + h * HEADDIM + p];
        yv *= z / (1.f + expf(-z));
        g_y[yi] = yv;
    }
}

// ---------------- RMSNorm over D_INNER + bf16 hi/lo split output ------------
__global__ __launch_bounds__(256) void rmsnorm_split_kernel(const float* __restrict__ norm_w)
{
    const int m = blockIdx.x;
    const int t = threadIdx.x;
    size_t base = (size_t)m * D_INNER;
    float s = 0.f;
    for (int i = t; i < D_INNER; i += 256) {
        float v = g_y[base + i];
        s += v * v;
    }
    __shared__ float red[256];
    red[t] = s; __syncthreads();
    for (int o = 128; o > 0; o >>= 1) {
        if (t < o) red[t] += red[t + o];
        __syncthreads();
    }
    float scale = rsqrtf(red[0] / (float)D_INNER + 1e-5f);
    for (int i = t; i < D_INNER; i += 256) {
        float v = g_y[base + i] * scale * norm_w[i];
        __nv_bfloat16 h = __float2bfloat16_rn(v);
        __nv_bfloat16 l = __float2bfloat16_rn(v - __bfloat162float(h));
        g_yhi[base + i] = *(unsigned short*)&h;
        g_ylo[base + i] = *(unsigned short*)&l;
    }
}

// ---------------- launch ----------------------------------------------------
extern "C" void kernel_launch(void* const* d_in, const int* in_sizes, int n_in,
                              void* d_out, int out_size)
{
    const float* u       = (const float*)d_in[0];
    const float* W_in    = (const float*)d_in[1];
    const float* conv_w  = (const float*)d_in[2];
    const float* conv_b  = (const float*)d_in[3];
    const float* dt_bias = (const float*)d_in[4];
    const float* A_log   = (const float*)d_in[5];
    const float* Dp      = (const float*)d_in[6];
    const float* norm_w  = (const float*)d_in[7];
    const float* W_out   = (const float*)d_in[8];
    float* out = (float*)d_out;

    float* zx;
    unsigned short *uhi, *ulo, *w1hi, *w1lo, *yhi, *ylo, *w2hi, *w2lo;
    cudaGetSymbolAddress((void**)&zx, g_zxbcdt);
    cudaGetSymbolAddress((void**)&uhi, g_uhi);
    cudaGetSymbolAddress((void**)&ulo, g_ulo);
    cudaGetSymbolAddress((void**)&w1hi, g_w1hi);
    cudaGetSymbolAddress((void**)&w1lo, g_w1lo);
    cudaGetSymbolAddress((void**)&yhi, g_yhi);
    cudaGetSymbolAddress((void**)&ylo, g_ylo);
    cudaGetSymbolAddress((void**)&w2hi, g_w2hi);
    cudaGetSymbolAddress((void**)&w2lo, g_w2lo);

    cudaFuncSetAttribute(bf16gemm3, cudaFuncAttributeMaxDynamicSharedMemorySize, GSMEM);

    // 0. split inputs to bf16 hi/lo
    split_kernel<<<(MTOT * D_MODEL) / 1024, 256>>>(u, uhi, ulo, MTOT * D_MODEL);
    split_kernel<<<(D_IN_PROJ * D_MODEL) / 1024, 256>>>(W_in, w1hi, w1lo, D_IN_PROJ * D_MODEL);
    split_kernel<<<(D_MODEL * D_INNER) / 1024, 256>>>(W_out, w2hi, w2lo, D_MODEL * D_INNER);

    // 1. in_proj:  zxbcdt = u @ W_in^T   (8192 x 4160 x 1024)
    bf16gemm3<<<dim3((D_IN_PROJ + BN - 1) / BN, MTOT / BM), NTHR, GSMEM>>>(
        uhi, ulo, w1hi, w1lo, zx, MTOT, D_IN_PROJ, D_MODEL);

    // 2. depthwise conv + silu on xBC slice
    conv_silu_kernel<<<(MTOT * CONV_DIM + 255) / 256, 256>>>(conv_w, conv_b);

    // 3. dt = softplus(raw + bias)
    dt_kernel<<<(MTOT * NHEADS + 255) / 256, 256>>>(dt_bias);

    // 4. SSD intra-chunk (Y_diag + chunk states)
    ssd_chunk_kernel<<<dim3(NCHUNK, NHEADS, BATCH), 256>>>(A_log);

    // 5. sequential cross-chunk scan
    ssd_scan_kernel<<<BATCH * NHEADS, 1024>>>();

    // 6. off-diagonal contribution + D*x + gating
    ssd_offdiag_kernel<<<dim3(NCHUNK, NHEADS, BATCH), 256>>>(Dp);

    // 7. RMSNorm (+ bf16 split of y for out_proj)
    rmsnorm_split_kernel<<<MTOT, 256>>>(norm_w);

    // 8. out_proj: out = y @ W_out^T   (8192 x 1024 x 2048)
    bf16gemm3<<<dim3(D_MODEL / BN, MTOT / BM), NTHR, GSMEM>>>(
        yhi, ylo, w2hi, w2lo, out, MTOT, D_MODEL, D_INNER);
}

// round 10
// speedup vs baseline: 2.8522x; 1.0697x over previous
#include <cuda_runtime.h>
#include <cuda_bf16.h>
#include <math.h>
#include <stdint.h>

#define D_MODEL   1024
#define D_STATE   16
#define D_CONV    4
#define HEADDIM   64
#define CHUNK     64
#define D_INNER   2048
#define NHEADS    32
#define CONV_DIM  2080          // D_INNER + 2*D_STATE
#define D_IN_PROJ 4160          // 2*D_INNER + 2*D_STATE + NHEADS
#define BATCH     2
#define SEQ       4096
#define NCHUNK    (SEQ / CHUNK) // 64
#define MTOT      (BATCH * SEQ) // 8192

// ---------------- scratch (device globals; no allocation allowed) -----------
__device__ float g_zxbcdt[(size_t)MTOT * D_IN_PROJ];
__device__ float g_xBC[(size_t)MTOT * CONV_DIM];
__device__ float g_dt[(size_t)MTOT * NHEADS];
__device__ float g_Acum[(size_t)BATCH * NCHUNK * NHEADS * CHUNK];
__device__ float g_cs[(size_t)BATCH * NCHUNK * NHEADS * HEADDIM * D_STATE];
__device__ float g_sp[(size_t)BATCH * NCHUNK * NHEADS * HEADDIM * D_STATE];
__device__ float g_y[(size_t)MTOT * D_INNER];

// bf16 hi/lo split buffers
__device__ unsigned short g_uhi[(size_t)MTOT * D_MODEL];
__device__ unsigned short g_ulo[(size_t)MTOT * D_MODEL];
__device__ unsigned short g_w1hi[(size_t)D_IN_PROJ * D_MODEL];
__device__ unsigned short g_w1lo[(size_t)D_IN_PROJ * D_MODEL];
__device__ unsigned short g_yhi[(size_t)MTOT * D_INNER];
__device__ unsigned short g_ylo[(size_t)MTOT * D_INNER];
__device__ unsigned short g_w2hi[(size_t)D_MODEL * D_INNER];
__device__ unsigned short g_w2lo[(size_t)D_MODEL * D_INNER];

// ============================================================================
// helpers
// ============================================================================
__device__ __forceinline__ uint32_t cvta_s(const void* p) {
    uint32_t a;
    asm("{ .reg .u64 t; cvta.to.shared.u64 t, %1; cvt.u32.u64 %0, t; }" : "=r"(a) : "l"(p));
    return a;
}
__device__ __forceinline__ void cpa16(uint32_t dst, const void* src, int sz) {
    asm volatile("cp.async.cg.shared.global [%0], [%1], 16, %2;"
                 :: "r"(dst), "l"(src), "r"(sz));
}
#define CP_COMMIT() asm volatile("cp.async.commit_group;" ::: "memory")
#define CP_WAIT1()  asm volatile("cp.async.wait_group 1;" ::: "memory")

__device__ __forceinline__ void ldm_x4(uint32_t& r0, uint32_t& r1, uint32_t& r2,
                                       uint32_t& r3, uint32_t addr) {
    asm volatile("ldmatrix.sync.aligned.m8n8.x4.shared.b16 {%0,%1,%2,%3}, [%4];"
                 : "=r"(r0), "=r"(r1), "=r"(r2), "=r"(r3) : "r"(addr));
}
__device__ __forceinline__ void mma_bf16(float* d, const uint32_t* a, const uint32_t* b) {
    asm volatile(
        "mma.sync.aligned.m16n8k16.row.col.f32.bf16.bf16.f32 "
        "{%0,%1,%2,%3},{%4,%5,%6,%7},{%8,%9},{%0,%1,%2,%3};"
        : "+f"(d[0]), "+f"(d[1]), "+f"(d[2]), "+f"(d[3])
        : "r"(a[0]), "r"(a[1]), "r"(a[2]), "r"(a[3]), "r"(b[0]), "r"(b[1]));
}

// ============================================================================
// bf16 3-term split GEMM: C[M,N] = A[M,K] @ B[N,K]^T (fp32 accuracy ~1e-5)
// Terms along K: [Ahi*Bhi | Ahi*Blo | Alo*Bhi]. CTA tile 128x128, BK=64,
// 128 threads (4 warps 2x2), warp tile 64x64, 3-stage cp.async pipeline.
// cp.async issue spread across the ks loop (A-half after ks0, B-half after ks1)
// to decongest the LSU at K-block heads. 2 CTAs resident per SM.
// ============================================================================
#define BM 128
#define BN 128
#define BKG 64
#define STG 3
#define NTHR 128
#define ATILE (BM * BKG * 2)       // 16384 B
#define BTILE (BN * BKG * 2)       // 16384 B
#define STGB (ATILE + BTILE)       // 32768 B
#define GSMEM (STG * STGB)         // 98304 B

__global__ __launch_bounds__(NTHR, 2) void bf16gemm3(
    const unsigned short* __restrict__ Ahi, const unsigned short* __restrict__ Alo,
    const unsigned short* __restrict__ Bhi, const unsigned short* __restrict__ Blo,
    float* __restrict__ C, int M, int N, int K)
{
    extern __shared__ char smraw[];
    const uint32_t smb = cvta_s(smraw);
    const int tid = threadIdx.x, lane = tid & 31, wid = tid >> 5;
    const int wm = (wid & 1) * 64, wn = (wid >> 1) * 64;
    const int qr = lane >> 2, qc = lane & 3;
    const int brow = blockIdx.y * BM, bcol = blockIdx.x * BN;
    const int KBblk = K >> 6, KBt = 3 * KBblk;

    float acc[4][8][4];
    #pragma unroll
    for (int mi = 0; mi < 4; mi++)
        #pragma unroll
        for (int ni = 0; ni < 8; ni++)
            #pragma unroll
            for (int r = 0; r < 4; r++) acc[mi][ni][r] = 0.f;

    auto srcsel = [&](int kb, const unsigned short*& pa, const unsigned short*& pb, int& kk) {
        if (kb < KBblk)          { pa = Ahi; pb = Bhi; kk = kb; }
        else if (kb < 2 * KBblk) { pa = Ahi; pb = Blo; kk = kb - KBblk; }
        else                     { pa = Alo; pb = Bhi; kk = kb - 2 * KBblk; }
    };
    auto issueA = [&](int kb) {
        if (kb >= KBt) return;
        const unsigned short *pa, *pb; int kk;
        srcsel(kb, pa, pb, kk);
        const uint32_t abase = smb + (kb % STG) * STGB;
        #pragma unroll
        for (int p = 0; p < 8; p++) {
            int g = tid + p * NTHR;
            int r = g >> 3, cg = g & 7;
            cpa16(abase + r * 128 + ((cg ^ (r & 7)) * 16),
                  pa + (size_t)(brow + r) * K + kk * BKG + cg * 8, 16);
        }
    };
    auto issueB = [&](int kb) {
        if (kb >= KBt) return;
        const unsigned short *pa, *pb; int kk;
        srcsel(kb, pa, pb, kk);
        const uint32_t bbase = smb + (kb % STG) * STGB + ATILE;
        #pragma unroll
        for (int p = 0; p < 8; p++) {
            int g = tid + p * NTHR;
            int r = g >> 3, cg = g & 7;
            int bn = bcol + r;
            cpa16(bbase + r * 128 + ((cg ^ (r & 7)) * 16),
                  pb + (size_t)(bn < N ? bn : 0) * K + kk * BKG + cg * 8,
                  bn < N ? 16 : 0);
        }
    };

    issueA(0); issueB(0); CP_COMMIT();
    issueA(1); issueB(1); CP_COMMIT();

    for (int kb = 0; kb < KBt; kb++) {
        CP_WAIT1();
        __syncthreads();

        const int st = kb % STG;
        const uint32_t abase = smb + st * STGB;
        const uint32_t bbase = abase + ATILE;
        #pragma unroll
        for (int ks = 0; ks < 4; ks++) {
            uint32_t af[4][4], bfr[8][2];
            #pragma unroll
            for (int mi = 0; mi < 4; mi++) {
                int r = wm + mi * 16 + (lane & 15);
                int g = (ks * 2 + (lane >> 4)) ^ (r & 7);
                ldm_x4(af[mi][0], af[mi][1], af[mi][2], af[mi][3],
                       abase + r * 128 + g * 16);
            }
            #pragma unroll
            for (int pi = 0; pi < 4; pi++) {
                int r = wn + pi * 16 + (lane & 7) + (((lane >> 4) & 1) << 3);
                int g = (ks * 2 + ((lane >> 3) & 1)) ^ (r & 7);
                ldm_x4(bfr[pi * 2][0], bfr[pi * 2][1],
                       bfr[pi * 2 + 1][0], bfr[pi * 2 + 1][1],
                       bbase + r * 128 + g * 16);
            }
            if (ks == 0) issueA(kb + 2);
            if (ks == 1) issueB(kb + 2);
            #pragma unroll
            for (int mi = 0; mi < 4; mi++)
                #pragma unroll
                for (int ni = 0; ni < 8; ni++)
                    mma_bf16(acc[mi][ni], af[mi], bfr[ni]);
        }
        CP_COMMIT();
    }

    // epilogue
    #pragma unroll
    for (int mi = 0; mi < 4; mi++) {
        int row0 = brow + wm + mi * 16 + qr;
        #pragma unroll
        for (int ni = 0; ni < 8; ni++) {
            int col = bcol + wn + ni * 8 + qc * 2;
            if (col < N) {
                *(float2*)(C + (size_t)row0 * N + col) =
                    make_float2(acc[mi][ni][0], acc[mi][ni][1]);
                *(float2*)(C + (size_t)(row0 + 8) * N + col) =
                    make_float2(acc[mi][ni][2], acc[mi][ni][3]);
            }
        }
    }
}

// ---------------- fp32 -> bf16 hi/lo split ----------------------------------
__global__ void split_kernel(const float* __restrict__ s,
                             unsigned short* __restrict__ hi,
                             unsigned short* __restrict__ lo, int n)
{
    int i = (blockIdx.x * 256 + threadIdx.x) * 4;
    if (i >= n) return;
    float4 v = *(const float4*)(s + i);
    __nv_bfloat16 h0 = __float2bfloat16_rn(v.x);
    __nv_bfloat16 h1 = __float2bfloat16_rn(v.y);
    __nv_bfloat16 h2 = __float2bfloat16_rn(v.z);
    __nv_bfloat16 h3 = __float2bfloat16_rn(v.w);
    __nv_bfloat16 l0 = __float2bfloat16_rn(v.x - __bfloat162float(h0));
    __nv_bfloat16 l1 = __float2bfloat16_rn(v.y - __bfloat162float(h1));
    __nv_bfloat16 l2 = __float2bfloat16_rn(v.z - __bfloat162float(h2));
    __nv_bfloat16 l3 = __float2bfloat16_rn(v.w - __bfloat162float(h3));
    *(ushort4*)(hi + i) = make_ushort4(*(unsigned short*)&h0, *(unsigned short*)&h1,
                                       *(unsigned short*)&h2, *(unsigned short*)&h3);
    *(ushort4*)(lo + i) = make_ushort4(*(unsigned short*)&l0, *(unsigned short*)&l1,
                                       *(unsigned short*)&l2, *(unsigned short*)&l3);
}

// ---------------- depthwise causal conv(4) + bias + SiLU --------------------
__global__ void conv_silu_kernel(const float* __restrict__ conv_w,
                                 const float* __restrict__ conv_b)
{
    int idx = blockIdx.x * blockDim.x + threadIdx.x;
    if (idx >= MTOT * CONV_DIM) return;
    int c = idx % CONV_DIM;
    int m = idx / CONV_DIM;
    int l = m & (SEQ - 1);

    float acc = conv_b[c];
    #pragma unroll
    for (int j = 0; j < D_CONV; j++) {
        int lj = l - (D_CONV - 1) + j;
        if (lj >= 0)
            acc += conv_w[c * D_CONV + j] *
                   g_zxbcdt[(size_t)(m - (D_CONV - 1) + j) * D_IN_PROJ + D_INNER + c];
    }
    g_xBC[idx] = acc / (1.f + expf(-acc));
}

// ---------------- dt = softplus(raw + bias) ---------------------------------
__global__ void dt_kernel(const float* __restrict__ dt_bias)
{
    int idx = blockIdx.x * blockDim.x + threadIdx.x;
    if (idx >= MTOT * NHEADS) return;
    int h = idx & (NHEADS - 1);
    int m = idx >> 5;
    float x = g_zxbcdt[(size_t)m * D_IN_PROJ + (D_IN_PROJ - NHEADS) + h] + dt_bias[h];
    g_dt[idx] = (x > 20.f) ? x : log1pf(expf(x));
}

// ---------------- SSD stage 1: per-chunk diag output + chunk states ---------
__global__ __launch_bounds__(256) void ssd_chunk_kernel(const float* __restrict__ A_log)
{
    __shared__ float xs[CHUNK][HEADDIM];
    __shared__ float Gs[CHUNK][CHUNK];
    __shared__ float Bsh[CHUNK][D_STATE];
    __shared__ float Csh[CHUNK][D_STATE];
    __shared__ float Acum[CHUNK];
    __shared__ float dts[CHUNK];
    __shared__ float decay[CHUNK];
    __shared__ float r4[CHUNK];          // r4[l] = exp(Acum[l+4]-Acum[l])

    const int c = blockIdx.x, h = blockIdx.y, b = blockIdx.z;
    const int t = threadIdx.x;
    const int m0 = b * SEQ + c * CHUNK;

    if (t < CHUNK) dts[t] = g_dt[(size_t)(m0 + t) * NHEADS + h];
    #pragma unroll
    for (int i = 0; i < 4; i++) {
        int idx = t + i * 256;
        int s = idx >> 4, n = idx & 15;
        Bsh[s][n] = g_xBC[(size_t)(m0 + s) * CONV_DIM + D_INNER + n];
        Csh[s][n] = g_xBC[(size_t)(m0 + s) * CONV_DIM + D_INNER + D_STATE + n];
    }
    __syncthreads();
    #pragma unroll
    for (int i = 0; i < 16; i++) {
        int idx = t + i * 256;
        int s = idx >> 6, p = idx & 63;
        xs[s][p] = g_xBC[(size_t)(m0 + s) * CONV_DIM + h * HEADDIM + p] * dts[s];
    }
    __syncthreads();

    if (t == 0) {
        float Ah = -expf(A_log[h]);
        float run = 0.f;
        for (int s = 0; s < CHUNK; s++) { run += Ah * dts[s]; Acum[s] = run; }
    }
    __syncthreads();
    float Alast = Acum[CHUNK - 1];
    if (t < CHUNK) {
        decay[t] = expf(Alast - Acum[t]);
        g_Acum[(((size_t)(b * NCHUNK) + c) * NHEADS + h) * CHUNK + t] = Acum[t];
        r4[t] = (t < CHUNK - 4) ? expf(Acum[t + 4] - Acum[t]) : 0.f;
    }
    __syncthreads();

    // G[l][s] = (C[l]·B[s]) * exp(Acum[l]-Acum[s]), s <= l.
    // Each thread: fixed s = t&63, l = (t>>6) + 4i. exp via seeded recurrence:
    // e(l+4) = e(l) * r4[l]; one expf per thread. B[s] row hoisted to registers.
    {
        const int s = t & 63;
        const int l0 = t >> 6;
        float4 Bq0 = *(const float4*)&Bsh[s][0];
        float4 Bq1 = *(const float4*)&Bsh[s][4];
        float4 Bq2 = *(const float4*)&Bsh[s][8];
        float4 Bq3 = *(const float4*)&Bsh[s][12];
        float As = Acum[s];
        float e = -1.f;
        #pragma unroll
        for (int i = 0; i < 16; i++) {
            int l = l0 + 4 * i;
            float g = 0.f;
            if (l >= s) {
                if (e < 0.f) e = expf(Acum[l] - As);
                else         e *= r4[l - 4];
                float4 c0 = *(const float4*)&Csh[l][0];
                float4 c1 = *(const float4*)&Csh[l][4];
                float4 c2 = *(const float4*)&Csh[l][8];
                float4 c3 = *(const float4*)&Csh[l][12];
                float d = c0.x * Bq0.x + c0.y * Bq0.y + c0.z * Bq0.z + c0.w * Bq0.w
                        + c1.x * Bq1.x + c1.y * Bq1.y + c1.z * Bq1.z + c1.w * Bq1.w
                        + c2.x * Bq2.x + c2.y * Bq2.y + c2.z * Bq2.z + c2.w * Bq2.w
                        + c3.x * Bq3.x + c3.y * Bq3.y + c3.z * Bq3.z + c3.w * Bq3.w;
                g = d * e;
            }
            Gs[l][s] = g;
        }
    }
    __syncthreads();

    // Y_diag = G @ x, s-unrolled by 4, all-float4 shared reads
    {
        const int p0 = (t & 15) * 4;
        const int l0 = (t >> 4) * 4;
        float acc[4][4];
        #pragma unroll
        for (int i = 0; i < 4; i++)
            #pragma unroll
            for (int j = 0; j < 4; j++) acc[i][j] = 0.f;
        for (int s0 = 0; s0 < CHUNK; s0 += 4) {
            float4 xq[4];
            #pragma unroll
            for (int j = 0; j < 4; j++) xq[j] = *(const float4*)&xs[s0 + j][p0];
            #pragma unroll
            for (int i = 0; i < 4; i++) {
                float4 gq = *(const float4*)&Gs[l0 + i][s0];
                acc[i][0] += gq.x * xq[0].x + gq.y * xq[1].x + gq.z * xq[2].x + gq.w * xq[3].x;
                acc[i][1] += gq.x * xq[0].y + gq.y * xq[1].y + gq.z * xq[2].y + gq.w * xq[3].y;
                acc[i][2] += gq.x * xq[0].z + gq.y * xq[1].z + gq.z * xq[2].z + gq.w * xq[3].z;
                acc[i][3] += gq.x * xq[0].w + gq.y * xq[1].w + gq.z * xq[2].w + gq.w * xq[3].w;
            }
        }
        #pragma unroll
        for (int i = 0; i < 4; i++)
            *(float4*)&g_y[(size_t)(m0 + l0 + i) * D_INNER + h * HEADDIM + p0] =
                make_float4(acc[i][0], acc[i][1], acc[i][2], acc[i][3]);
    }

    {
        const int p  = t & 63;
        const int nb = (t >> 6) * 4;
        float acc[4] = {0.f, 0.f, 0.f, 0.f};
        for (int s = 0; s < CHUNK; s++) {
            float xv = xs[s][p] * decay[s];
            #pragma unroll
            for (int j = 0; j < 4; j++) acc[j] += Bsh[s][nb + j] * xv;
        }
        size_t base = ((((size_t)(b * NCHUNK) + c) * NHEADS + h) * HEADDIM + p) * D_STATE + nb;
        #pragma unroll
        for (int j = 0; j < 4; j++) g_cs[base + j] = acc[j];
    }
}

// ---------------- SSD stage 2: sequential cross-chunk state scan ------------
__global__ __launch_bounds__(1024) void ssd_scan_kernel()
{
    const int bh = blockIdx.x;
    const int b = bh / NHEADS, h = bh % NHEADS;
    const int t = threadIdx.x;
    float state = 0.f;
    for (int c = 0; c < NCHUNK; c++) {
        size_t base = (((size_t)(b * NCHUNK) + c) * NHEADS + h) * (HEADDIM * D_STATE);
        g_sp[base + t] = state;
        float dA = expf(g_Acum[(((size_t)(b * NCHUNK) + c) * NHEADS + h) * CHUNK + (CHUNK - 1)]);
        state = state * dA + g_cs[base + t];
    }
}

// ---------------- SSD stage 3: off-diag + D*x + gate(silu(z)) ---------------
__global__ __launch_bounds__(256) void ssd_offdiag_kernel(const float* __restrict__ Dp)
{
    __shared__ float sp[CHUNK][D_STATE];
    __shared__ float Csh[CHUNK][D_STATE];
    __shared__ float eA[CHUNK];

    const int c = blockIdx.x, h = blockIdx.y, b = blockIdx.z;
    const int t = threadIdx.x;
    const int m0 = b * SEQ + c * CHUNK;
    size_t spbase = (((size_t)(b * NCHUNK) + c) * NHEADS + h) * (HEADDIM * D_STATE);

    #pragma unroll
    for (int i = 0; i < 4; i++) {
        int idx = t + i * 256;
        ((float*)sp)[idx] = g_sp[spbase + idx];
        int s = idx >> 4, n = idx & 15;
        Csh[s][n] = g_xBC[(size_t)(m0 + s) * CONV_DIM + D_INNER + D_STATE + n];
    }
    if (t < CHUNK)
        eA[t] = expf(g_Acum[(((size_t)(b * NCHUNK) + c) * NHEADS + h) * CHUNK + t]);
    __syncthreads();

    const float Dh = Dp[h];
    const int p = t & 63;
    const int lbase = (t >> 6) * 16;

    float spr[D_STATE];
    #pragma unroll
    for (int n = 0; n < D_STATE; n++) spr[n] = sp[p][n];

    for (int i = 0; i < 16; i++) {
        int l = lbase + i;
        int m = m0 + l;
        float d = 0.f;
        #pragma unroll
        for (int n = 0; n < D_STATE; n++) d += Csh[l][n] * spr[n];
        size_t yi = (size_t)m * D_INNER + h * HEADDIM + p;
        float yv = g_y[yi] + eA[l] * d;
        yv += Dh * g_xBC[(size_t)m * CONV_DIM + h * HEADDIM + p];
        float z = g_zxbcdt[(size_t)m * D_IN_PROJ + h * HEADDIM + p];
        yv *= z / (1.f + expf(-z));
        g_y[yi] = yv;
    }
}

// ---------------- RMSNorm over D_INNER + bf16 hi/lo split output ------------
__global__ __launch_bounds__(256) void rmsnorm_split_kernel(const float* __restrict__ norm_w)
{
    const int m = blockIdx.x;
    const int t = threadIdx.x;
    size_t base = (size_t)m * D_INNER;
    float s = 0.f;
    for (int i = t; i < D_INNER; i += 256) {
        float v = g_y[base + i];
        s += v * v;
    }
    __shared__ float red[256];
    red[t] = s; __syncthreads();
    for (int o = 128; o > 0; o >>= 1) {
        if (t < o) red[t] += red[t + o];
        __syncthreads();
    }
    float scale = rsqrtf(red[0] / (float)D_INNER + 1e-5f);
    for (int i = t; i < D_INNER; i += 256) {
        float v = g_y[base + i] * scale * norm_w[i];
        __nv_bfloat16 h = __float2bfloat16_rn(v);
        __nv_bfloat16 l = __float2bfloat16_rn(v - __bfloat162float(h));
        g_yhi[base + i] = *(unsigned short*)&h;
        g_ylo[base + i] = *(unsigned short*)&l;
    }
}

// ---------------- launch ----------------------------------------------------
extern "C" void kernel_launch(void* const* d_in, const int* in_sizes, int n_in,
                              void* d_out, int out_size)
{
    const float* u       = (const float*)d_in[0];
    const float* W_in    = (const float*)d_in[1];
    const float* conv_w  = (const float*)d_in[2];
    const float* conv_b  = (const float*)d_in[3];
    const float* dt_bias = (const float*)d_in[4];
    const float* A_log   = (const float*)d_in[5];
    const float* Dp      = (const float*)d_in[6];
    const float* norm_w  = (const float*)d_in[7];
    const float* W_out   = (const float*)d_in[8];
    float* out = (float*)d_out;

    float* zx;
    unsigned short *uhi, *ulo, *w1hi, *w1lo, *yhi, *ylo, *w2hi, *w2lo;
    cudaGetSymbolAddress((void**)&zx, g_zxbcdt);
    cudaGetSymbolAddress((void**)&uhi, g_uhi);
    cudaGetSymbolAddress((void**)&ulo, g_ulo);
    cudaGetSymbolAddress((void**)&w1hi, g_w1hi);
    cudaGetSymbolAddress((void**)&w1lo, g_w1lo);
    cudaGetSymbolAddress((void**)&yhi, g_yhi);
    cudaGetSymbolAddress((void**)&ylo, g_ylo);
    cudaGetSymbolAddress((void**)&w2hi, g_w2hi);
    cudaGetSymbolAddress((void**)&w2lo, g_w2lo);

    cudaFuncSetAttribute(bf16gemm3, cudaFuncAttributeMaxDynamicSharedMemorySize, GSMEM);

    // 0. split inputs to bf16 hi/lo
    split_kernel<<<(MTOT * D_MODEL) / 1024, 256>>>(u, uhi, ulo, MTOT * D_MODEL);
    split_kernel<<<(D_IN_PROJ * D_MODEL) / 1024, 256>>>(W_in, w1hi, w1lo, D_IN_PROJ * D_MODEL);
    split_kernel<<<(D_MODEL * D_INNER) / 1024, 256>>>(W_out, w2hi, w2lo, D_MODEL * D_INNER);

    // 1. in_proj:  zxbcdt = u @ W_in^T   (8192 x 4160 x 1024)
    bf16gemm3<<<dim3((D_IN_PROJ + BN - 1) / BN, MTOT / BM), NTHR, GSMEM>>>(
        uhi, ulo, w1hi, w1lo, zx, MTOT, D_IN_PROJ, D_MODEL);

    // 2. depthwise conv + silu on xBC slice
    conv_silu_kernel<<<(MTOT * CONV_DIM + 255) / 256, 256>>>(conv_w, conv_b);

    // 3. dt = softplus(raw + bias)
    dt_kernel<<<(MTOT * NHEADS + 255) / 256, 256>>>(dt_bias);

    // 4. SSD intra-chunk (Y_diag + chunk states)
    ssd_chunk_kernel<<<dim3(NCHUNK, NHEADS, BATCH), 256>>>(A_log);

    // 5. sequential cross-chunk scan
    ssd_scan_kernel<<<BATCH * NHEADS, 1024>>>();

    // 6. off-diagonal contribution + D*x + gating
    ssd_offdiag_kernel<<<dim3(NCHUNK, NHEADS, BATCH), 256>>>(Dp);

    // 7. RMSNorm (+ bf16 split of y for out_proj)
    rmsnorm_split_kernel<<<MTOT, 256>>>(norm_w);

    // 8. out_proj: out = y @ W_out^T   (8192 x 1024 x 2048)
    bf16gemm3<<<dim3(D_MODEL / BN, MTOT / BM), NTHR, GSMEM>>>(
        yhi, ylo, w2hi, w2lo, out, MTOT, D_MODEL, D_INNER);
}